// round 1
// baseline (speedup 1.0000x reference)
#include <cuda_runtime.h>

// ---------------------------------------------------------------------------
// DeBERTa-style disentangled attention, fp32 baseline.
// B=8 S=384 IN=512 E=512 H=8 D=64, rel offsets t in [0,767), table row t+128.
// ---------------------------------------------------------------------------

#define KB 8
#define KS 384
#define KIN 512
#define KE 512
#define KH 8
#define KD 64
#define KT 767            // 2*S-1
#define KRELOFF 128       // table row = t + 128
#define KSCALE 0.07216878364870323f   // 1/sqrt(64*3)

__device__ float g_q[KB*KH*KS*KD];
__device__ float g_k[KB*KH*KS*KD];
__device__ float g_v[KB*KH*KS*KD];
__device__ float g_pk[KH*KT*KD];
__device__ float g_pq[KH*KT*KD];
__device__ float g_c2p[(size_t)KB*KH*KS*KT];
__device__ float g_p2c[(size_t)KB*KH*KS*KT];
__device__ float g_ctx[KB*KS*KE];

// ---------------------------------------------------------------------------
// 64x64 tile fp32 GEMM core: acc[r][c] += sum_k A[a0+4*ty+r][k] * Bm[b0+4*tx+c][k]
// A: [Mlim x lda] row-major, Bm: [Nlim x ldb] row-major (we compute A @ Bm^T).
// 256 threads, BK=16, smem As/Bs are 16*68 floats each (caller-provided).
// ---------------------------------------------------------------------------
__device__ __forceinline__ void sgemm64_core(
    const float* __restrict__ A, int lda, int a0, int Mlim,
    const float* __restrict__ Bm, int ldb, int b0, int Nlim,
    int K, float acc[4][4], float* As, float* Bs)
{
    const int tid = threadIdx.x;
    const int tx = tid & 15, ty = tid >> 4;
    const int lr = tid >> 2;           // 0..63 tile row for loads
    const int lk = (tid & 3) * 4;      // k offset for loads

    for (int k0 = 0; k0 < K; k0 += 16) {
        __syncthreads();
        {
            int row = a0 + lr;
            float4 v = make_float4(0.f, 0.f, 0.f, 0.f);
            if (row < Mlim)
                v = *(const float4*)(A + (size_t)row * lda + k0 + lk);
            As[(lk+0)*68 + lr] = v.x; As[(lk+1)*68 + lr] = v.y;
            As[(lk+2)*68 + lr] = v.z; As[(lk+3)*68 + lr] = v.w;
        }
        {
            int row = b0 + lr;
            float4 v = make_float4(0.f, 0.f, 0.f, 0.f);
            if (row < Nlim)
                v = *(const float4*)(Bm + (size_t)row * ldb + k0 + lk);
            Bs[(lk+0)*68 + lr] = v.x; Bs[(lk+1)*68 + lr] = v.y;
            Bs[(lk+2)*68 + lr] = v.z; Bs[(lk+3)*68 + lr] = v.w;
        }
        __syncthreads();
        #pragma unroll
        for (int kk = 0; kk < 16; kk++) {
            float4 a4 = *(const float4*)&As[kk*68 + ty*4];
            float4 b4 = *(const float4*)&Bs[kk*68 + tx*4];
            float av[4] = {a4.x, a4.y, a4.z, a4.w};
            float bv[4] = {b4.x, b4.y, b4.z, b4.w};
            #pragma unroll
            for (int r = 0; r < 4; r++)
                #pragma unroll
                for (int c = 0; c < 4; c++)
                    acc[r][c] = fmaf(av[r], bv[c], acc[r][c]);
        }
    }
}

// ---------------------------------------------------------------------------
// K1: fused QKV projection.  out[m][n] = x[m] . W[n] + b[n]
// grid (1536/64, 3072/64) — each N-tile lies fully inside one of Wq/Wk/Wv.
// Scatter to [b,h,s,d] layout.
// ---------------------------------------------------------------------------
__global__ void qkv_kernel(const float* __restrict__ x,
                           const float* __restrict__ Wq, const float* __restrict__ bq,
                           const float* __restrict__ Wk, const float* __restrict__ bk,
                           const float* __restrict__ Wv, const float* __restrict__ bv)
{
    __shared__ float As[16*68], Bs[16*68];
    const int m0 = blockIdx.y * 64;
    const int n0 = blockIdx.x * 64;
    const int which = n0 >> 9;
    const float* W    = (which == 0) ? Wq : (which == 1) ? Wk : Wv;
    const float* bias = (which == 0) ? bq : (which == 1) ? bk : bv;
    float* dst        = (which == 0) ? g_q : (which == 1) ? g_k : g_v;
    const int e0 = n0 & 511;

    float acc[4][4] = {};
    sgemm64_core(x, KIN, m0, KB*KS, W, KIN, e0, KE, KIN, acc, As, Bs);

    const int tx = threadIdx.x & 15, ty = threadIdx.x >> 4;
    #pragma unroll
    for (int r = 0; r < 4; r++) {
        const int m = m0 + ty*4 + r;
        const int b = m / KS, s = m % KS;
        #pragma unroll
        for (int c = 0; c < 4; c++) {
            const int e = e0 + tx*4 + c;
            const int h = e >> 6, d = e & 63;
            dst[((size_t)(b*KH + h)*KS + s)*KD + d] = acc[r][c] + bias[e];
        }
    }
}

// ---------------------------------------------------------------------------
// K2: positional projections PK[t] / PQ[t], t in [0,767).
// grid (1024/64, ceil(767/64)=12).
// ---------------------------------------------------------------------------
__global__ void pos_kernel(const float* __restrict__ rel_table,
                           const float* __restrict__ Wpk, const float* __restrict__ bpk,
                           const float* __restrict__ Wpq, const float* __restrict__ bpq)
{
    __shared__ float As[16*68], Bs[16*68];
    const int m0 = blockIdx.y * 64;
    const int n0 = blockIdx.x * 64;
    const bool isq = (n0 >= 512);
    const float* W    = isq ? Wpq : Wpk;
    const float* bias = isq ? bpq : bpk;
    float* dst        = isq ? g_pq : g_pk;
    const int e0 = n0 & 511;

    float acc[4][4] = {};
    sgemm64_core(rel_table + (size_t)KRELOFF*KIN, KIN, m0, KT,
                 W, KIN, e0, KE, KIN, acc, As, Bs);

    const int tx = threadIdx.x & 15, ty = threadIdx.x >> 4;
    #pragma unroll
    for (int r = 0; r < 4; r++) {
        const int t = m0 + ty*4 + r;
        if (t >= KT) continue;
        #pragma unroll
        for (int c = 0; c < 4; c++) {
            const int e = e0 + tx*4 + c;
            const int h = e >> 6, d = e & 63;
            dst[((size_t)h*KT + t)*KD + d] = acc[r][c] + bias[e];
        }
    }
}

// ---------------------------------------------------------------------------
// K3/K4: disentangled score tables.
//   which==0: C2P[bh][i][t] = q[bh][i] . PK[h][t]
//   which==1: P2C[bh][j][t] = k[bh][j] . PQ[h][t]
// grid (12, 6, 64).
// ---------------------------------------------------------------------------
__global__ void disent_kernel(int which)
{
    __shared__ float As[16*68], Bs[16*68];
    const int bh = blockIdx.z;
    const int h  = bh & 7;
    const int i0 = blockIdx.y * 64;
    const int t0 = blockIdx.x * 64;
    const float* vecs = which ? g_k  : g_q;
    const float* pos  = which ? g_pq : g_pk;
    float*       out  = which ? g_p2c : g_c2p;

    float acc[4][4] = {};
    sgemm64_core(vecs + (size_t)bh*KS*KD, KD, i0, KS,
                 pos  + (size_t)h*KT*KD,  KD, t0, KT, KD, acc, As, Bs);

    const int tx = threadIdx.x & 15, ty = threadIdx.x >> 4;
    #pragma unroll
    for (int r = 0; r < 4; r++) {
        const int i = i0 + ty*4 + r;
        #pragma unroll
        for (int c = 0; c < 4; c++) {
            const int t = t0 + tx*4 + c;
            if (t < KT)
                out[((size_t)bh*KS + i)*KT + t] = acc[r][c];
        }
    }
}

// ---------------------------------------------------------------------------
// K5: flash attention per (i-tile=64, h, b).  Online softmax over 6 j-tiles.
// logits = (qk + c2p_gather + p2c_gather) * SCALE, mask fill -9e15.
// ---------------------------------------------------------------------------
__global__ void attn_kernel(const int* __restrict__ mask)
{
    __shared__ float As[16*68], Bs[16*68];
    __shared__ float Ss[64*65];
    __shared__ float Vs[64*68];          // aliased: p2c band stage, then V tile
    __shared__ float row_m[64], row_l[64], alpha_s[64];
    __shared__ float red[64*4];
    __shared__ int   msks[64];

    const int i0 = blockIdx.x * 64;
    const int h  = blockIdx.y;
    const int b  = blockIdx.z;
    const int bh = b*KH + h;
    const float* qb   = g_q + (size_t)bh*KS*KD;
    const float* kb   = g_k + (size_t)bh*KS*KD;
    const float* vb   = g_v + (size_t)bh*KS*KD;
    const float* c2pb = g_c2p + (size_t)bh*KS*KT;
    const float* p2cb = g_p2c + (size_t)bh*KS*KT;

    const int tid = threadIdx.x;
    const int tx = tid & 15, ty = tid >> 4;
    const int rrow = tid >> 2, q4 = tid & 3;   // softmax: 4 threads per row

    float o[4][4] = {};
    if (tid < 64) { row_m[tid] = -1e30f; row_l[tid] = 0.f; }

    for (int j0 = 0; j0 < KS; j0 += 64) {
        // ---- stage p2c diagonal band into Vs (coalesced per j-row) ----
        __syncthreads();   // Vs free (prev P@V done / first iter)
        {
            const int c = rrow;                     // local j
            const int j = j0 + c;
            const float* src = p2cb + (size_t)j*KT + (j - i0 + 320);
            #pragma unroll
            for (int xx = 0; xx < 16; xx++) {
                const int x = q4 + xx*4;
                Vs[c*68 + x] = src[x];              // t = j-i0+320+x ; x = 63-r
            }
        }
        if (tid < 64) msks[tid] = mask[b*KS + j0 + tid];
        __syncthreads();

        // ---- init acc with c2p (gmem gather) + p2c (staged) ----
        float acc[4][4];
        #pragma unroll
        for (int r = 0; r < 4; r++) {
            const int i = i0 + ty*4 + r;
            const float* crow = c2pb + (size_t)i*KT + (j0 - i + 383);
            #pragma unroll
            for (int c = 0; c < 4; c++) {
                const int jl = tx*4 + c;
                acc[r][c] = crow[jl] + Vs[jl*68 + 63 - (ty*4 + r)];
            }
        }

        // ---- c2c: q @ k^T ----
        sgemm64_core(qb, KD, i0, KS, kb, KD, j0, KS, KD, acc, As, Bs);

        // ---- scale + mask, write S tile ----
        #pragma unroll
        for (int r = 0; r < 4; r++)
            #pragma unroll
            for (int c = 0; c < 4; c++) {
                float v = acc[r][c] * KSCALE;
                if (msks[tx*4 + c] == 0) v = -9e15f;
                Ss[(ty*4 + r)*65 + tx*4 + c] = v;
            }
        __syncthreads();

        // ---- online softmax (4 threads/row) ----
        {
            float mx = -1e30f;
            #pragma unroll
            for (int jj = q4*16; jj < q4*16 + 16; jj++)
                mx = fmaxf(mx, Ss[rrow*65 + jj]);
            red[rrow*4 + q4] = mx;
        }
        __syncthreads();
        if (q4 == 0) {
            float mn = fmaxf(fmaxf(red[rrow*4+0], red[rrow*4+1]),
                             fmaxf(red[rrow*4+2], red[rrow*4+3]));
            mn = fmaxf(mn, row_m[rrow]);
            alpha_s[rrow] = __expf(row_m[rrow] - mn);
            row_m[rrow] = mn;
        }
        __syncthreads();
        {
            const float mn = row_m[rrow];
            float s = 0.f;
            #pragma unroll
            for (int jj = q4*16; jj < q4*16 + 16; jj++) {
                float p = __expf(Ss[rrow*65 + jj] - mn);
                Ss[rrow*65 + jj] = p;
                s += p;
            }
            red[rrow*4 + q4] = s;
        }
        __syncthreads();
        if (q4 == 0)
            row_l[rrow] = row_l[rrow]*alpha_s[rrow]
                        + red[rrow*4+0] + red[rrow*4+1] + red[rrow*4+2] + red[rrow*4+3];

        // ---- load V tile into Vs (band consumed already) ----
        {
            const int c = rrow, d0 = q4 * 16;
            const float* src = vb + (size_t)(j0 + c)*KD + d0;
            #pragma unroll
            for (int dd = 0; dd < 16; dd += 4)
                *(float4*)&Vs[c*68 + d0 + dd] = *(const float4*)(src + dd);
        }
        __syncthreads();

        // ---- rescale O, accumulate P @ V ----
        float al[4];
        #pragma unroll
        for (int r = 0; r < 4; r++) al[r] = alpha_s[ty*4 + r];
        #pragma unroll
        for (int r = 0; r < 4; r++)
            #pragma unroll
            for (int c = 0; c < 4; c++) o[r][c] *= al[r];

        #pragma unroll
        for (int jj = 0; jj < 64; jj++) {
            float pv[4];
            #pragma unroll
            for (int r = 0; r < 4; r++) pv[r] = Ss[(ty*4 + r)*65 + jj];
            float4 vv = *(const float4*)&Vs[jj*68 + tx*4];
            float vvv[4] = {vv.x, vv.y, vv.z, vv.w};
            #pragma unroll
            for (int r = 0; r < 4; r++)
                #pragma unroll
                for (int c = 0; c < 4; c++)
                    o[r][c] = fmaf(pv[r], vvv[c], o[r][c]);
        }
    }

    // ---- normalize, store ctx [b][s][h*D+d] ----
    float inv[4];
    #pragma unroll
    for (int r = 0; r < 4; r++) inv[r] = 1.f / row_l[ty*4 + r];
    #pragma unroll
    for (int r = 0; r < 4; r++) {
        const int i = i0 + ty*4 + r;
        #pragma unroll
        for (int c = 0; c < 4; c++)
            g_ctx[((size_t)b*KS + i)*KE + h*KD + tx*4 + c] = o[r][c] * inv[r];
    }
}

// ---------------------------------------------------------------------------
// K6: output projection: out = ctx @ Wo^T + bo
// ---------------------------------------------------------------------------
__global__ void out_kernel(const float* __restrict__ Wo, const float* __restrict__ bo,
                           float* __restrict__ out)
{
    __shared__ float As[16*68], Bs[16*68];
    const int m0 = blockIdx.y * 64;
    const int n0 = blockIdx.x * 64;

    float acc[4][4] = {};
    sgemm64_core(g_ctx, KE, m0, KB*KS, Wo, KE, n0, KIN, KE, acc, As, Bs);

    const int tx = threadIdx.x & 15, ty = threadIdx.x >> 4;
    #pragma unroll
    for (int r = 0; r < 4; r++) {
        const int m = m0 + ty*4 + r;
        #pragma unroll
        for (int c = 0; c < 4; c++) {
            const int n = n0 + tx*4 + c;
            out[(size_t)m*KIN + n] = acc[r][c] + bo[n];
        }
    }
}

// ---------------------------------------------------------------------------
extern "C" void kernel_launch(void* const* d_in, const int* in_sizes, int n_in,
                              void* d_out, int out_size)
{
    const float* x    = (const float*)d_in[0];
    const int*   mask = (const int*)  d_in[1];
    const float* Wq   = (const float*)d_in[2];
    const float* bq   = (const float*)d_in[3];
    const float* Wk   = (const float*)d_in[4];
    const float* bk   = (const float*)d_in[5];
    const float* Wv   = (const float*)d_in[6];
    const float* bv   = (const float*)d_in[7];
    const float* rel  = (const float*)d_in[8];
    const float* Wpk  = (const float*)d_in[9];
    const float* bpk  = (const float*)d_in[10];
    const float* Wpq  = (const float*)d_in[11];
    const float* bpq  = (const float*)d_in[12];
    const float* Wo   = (const float*)d_in[13];
    const float* bo   = (const float*)d_in[14];

    dim3 thr(256);
    qkv_kernel   <<<dim3(1536/64, (KB*KS)/64), thr>>>(x, Wq, bq, Wk, bk, Wv, bv);
    pos_kernel   <<<dim3(1024/64, (KT + 63)/64), thr>>>(rel, Wpk, bpk, Wpq, bpq);
    disent_kernel<<<dim3((KT + 63)/64, KS/64, KB*KH), thr>>>(0);
    disent_kernel<<<dim3((KT + 63)/64, KS/64, KB*KH), thr>>>(1);
    attn_kernel  <<<dim3(KS/64, KH, KB), thr>>>(mask);
    out_kernel   <<<dim3(KIN/64, (KB*KS)/64), thr>>>(Wo, bo, (float*)d_out);
}

// round 6
// speedup vs baseline: 1.1371x; 1.1371x over previous
#include <cuda_runtime.h>

// ---------------------------------------------------------------------------
// DeBERTa-style disentangled attention, fp32.
// B=8 S=384 IN=512 E=512 H=8 D=64, rel offsets t in [0,767), table row t+128.
// R5: fix disent tile-skip window for p2c (row=j, window [j0, j_max+383]);
//     c2p keeps [383-i_max, 766-i0]. R4's misapplied c2p window zeroed part
//     of p2c -> rel_err 1.3e-3.
// ---------------------------------------------------------------------------

#define KB 8
#define KS 384
#define KIN 512
#define KE 512
#define KH 8
#define KD 64
#define KT 767            // 2*S-1 (logical)
#define KTP 768           // padded row stride for c2p/p2c scratch
#define KRELOFF 128       // table row = t + 128
#define KSCALE 0.07216878364870323f   // 1/sqrt(64*3)

#define PAD 132           // smem row stride for 128-wide tiles

__device__ float g_q[KB*KH*KS*KD];
__device__ float g_k[KB*KH*KS*KD];
__device__ float g_v[KB*KH*KS*KD];
__device__ float g_pk[KH*KT*KD];
__device__ float g_pq[KH*KT*KD];
__device__ float g_c2p[(size_t)KB*KH*KS*KTP];
__device__ float g_p2c[(size_t)KB*KH*KS*KTP];
__device__ float g_ctx[KB*KS*KE];

// ---------------------------------------------------------------------------
// 128x128 tile fp32 GEMM core, 256 threads, 8x8 per thread, BK=16.
// acc[r][c] += sum_k A[a0+ty*8+r][k] * Bm[b0+tx*8+c][k]   (A @ Bm^T)
// As/Bs: 16*PAD floats each (caller-provided smem).
// ---------------------------------------------------------------------------
__device__ __forceinline__ void sgemm128_core(
    const float* __restrict__ A, int lda, int a0, int Mlim,
    const float* __restrict__ Bm, int ldb, int b0, int Nlim,
    int K, float acc[8][8], float* As, float* Bs)
{
    const int tid = threadIdx.x;
    const int tx = tid & 15, ty = tid >> 4;
    const int lr = tid >> 2;           // 0..63
    const int lk = (tid & 3) * 4;      // 0,4,8,12

    for (int k0 = 0; k0 < K; k0 += 16) {
        __syncthreads();
        #pragma unroll
        for (int half = 0; half < 2; half++) {
            const int row = lr + half * 64;
            {
                const int ar = a0 + row;
                float4 v = make_float4(0.f, 0.f, 0.f, 0.f);
                if (ar < Mlim)
                    v = *(const float4*)(A + (size_t)ar * lda + k0 + lk);
                As[(lk+0)*PAD + row] = v.x; As[(lk+1)*PAD + row] = v.y;
                As[(lk+2)*PAD + row] = v.z; As[(lk+3)*PAD + row] = v.w;
            }
            {
                const int br = b0 + row;
                float4 v = make_float4(0.f, 0.f, 0.f, 0.f);
                if (br < Nlim)
                    v = *(const float4*)(Bm + (size_t)br * ldb + k0 + lk);
                Bs[(lk+0)*PAD + row] = v.x; Bs[(lk+1)*PAD + row] = v.y;
                Bs[(lk+2)*PAD + row] = v.z; Bs[(lk+3)*PAD + row] = v.w;
            }
        }
        __syncthreads();
        #pragma unroll
        for (int kk = 0; kk < 16; kk++) {
            float a8[8], b8[8];
            *(float4*)&a8[0] = *(const float4*)&As[kk*PAD + ty*8];
            *(float4*)&a8[4] = *(const float4*)&As[kk*PAD + ty*8 + 4];
            *(float4*)&b8[0] = *(const float4*)&Bs[kk*PAD + tx*8];
            *(float4*)&b8[4] = *(const float4*)&Bs[kk*PAD + tx*8 + 4];
            #pragma unroll
            for (int r = 0; r < 8; r++)
                #pragma unroll
                for (int c = 0; c < 8; c++)
                    acc[r][c] = fmaf(a8[r], b8[c], acc[r][c]);
        }
    }
}

// ---------------------------------------------------------------------------
// K1: fused QKV projection.  out[m][n] = x[m] . W[n] + b[n]
// grid (1536/128=12, 3072/128=24); each N-tile lies inside one of Wq/Wk/Wv.
// ---------------------------------------------------------------------------
__global__ void __launch_bounds__(256, 2)
qkv_kernel(const float* __restrict__ x,
           const float* __restrict__ Wq, const float* __restrict__ bq,
           const float* __restrict__ Wk, const float* __restrict__ bk,
           const float* __restrict__ Wv, const float* __restrict__ bv)
{
    __shared__ float As[16*PAD], Bs[16*PAD];
    const int m0 = blockIdx.y * 128;
    const int n0 = blockIdx.x * 128;
    const int which = n0 >> 9;
    const float* W    = (which == 0) ? Wq : (which == 1) ? Wk : Wv;
    const float* bias = (which == 0) ? bq : (which == 1) ? bk : bv;
    float* dst        = (which == 0) ? g_q : (which == 1) ? g_k : g_v;
    const int e0 = n0 & 511;

    float acc[8][8] = {};
    sgemm128_core(x, KIN, m0, KB*KS, W, KIN, e0, KE, KIN, acc, As, Bs);

    const int tx = threadIdx.x & 15, ty = threadIdx.x >> 4;
    const int ebase = e0 + tx*8;
    const int h = ebase >> 6, d0 = ebase & 63;   // 8 cols stay in one head
    #pragma unroll
    for (int r = 0; r < 8; r++) {
        const int m = m0 + ty*8 + r;
        const int b = m / KS, s = m % KS;
        float* drow = dst + ((size_t)(b*KH + h)*KS + s)*KD + d0;
        #pragma unroll
        for (int cc = 0; cc < 8; cc += 4) {
            float4 v;
            v.x = acc[r][cc+0] + bias[ebase+cc+0];
            v.y = acc[r][cc+1] + bias[ebase+cc+1];
            v.z = acc[r][cc+2] + bias[ebase+cc+2];
            v.w = acc[r][cc+3] + bias[ebase+cc+3];
            *(float4*)(drow + cc) = v;
        }
    }
}

// ---------------------------------------------------------------------------
// K2: positional projections PK[t] / PQ[t], t in [0,767).
// grid (1024/128=8, ceil(767/128)=6).
// ---------------------------------------------------------------------------
__global__ void __launch_bounds__(256, 2)
pos_kernel(const float* __restrict__ rel_table,
           const float* __restrict__ Wpk, const float* __restrict__ bpk,
           const float* __restrict__ Wpq, const float* __restrict__ bpq)
{
    __shared__ float As[16*PAD], Bs[16*PAD];
    const int m0 = blockIdx.y * 128;
    const int n0 = blockIdx.x * 128;
    const bool isq = (n0 >= 512);
    const float* W    = isq ? Wpq : Wpk;
    const float* bias = isq ? bpq : bpk;
    float* dst        = isq ? g_pq : g_pk;
    const int e0 = n0 & 511;

    float acc[8][8] = {};
    sgemm128_core(rel_table + (size_t)KRELOFF*KIN, KIN, m0, KT,
                  W, KIN, e0, KE, KIN, acc, As, Bs);

    const int tx = threadIdx.x & 15, ty = threadIdx.x >> 4;
    const int ebase = e0 + tx*8;
    const int h = ebase >> 6, d0 = ebase & 63;
    #pragma unroll
    for (int r = 0; r < 8; r++) {
        const int t = m0 + ty*8 + r;
        if (t >= KT) continue;
        float* drow = dst + ((size_t)h*KT + t)*KD + d0;
        #pragma unroll
        for (int cc = 0; cc < 8; cc += 4) {
            float4 v;
            v.x = acc[r][cc+0] + bias[ebase+cc+0];
            v.y = acc[r][cc+1] + bias[ebase+cc+1];
            v.z = acc[r][cc+2] + bias[ebase+cc+2];
            v.w = acc[r][cc+3] + bias[ebase+cc+3];
            *(float4*)(drow + cc) = v;
        }
    }
}

// ---------------------------------------------------------------------------
// K3/K4: disentangled score tables with t-window tile skipping.
//   which==0: C2P[bh][i][t] = q[bh][i] . PK[h][t]
//             attn reads t = j-i+383, j in [0,384) -> block window
//             [383 - i_max, 766 - i0]
//   which==1: P2C[bh][j][t] = k[bh][j] . PQ[h][t]
//             attn reads t = j-i+383, i in [0,384) -> block window
//             [j0, j_max + 383]
// Scratch row stride = KTP=768 so all float4 stores are 16B-aligned.
// grid (6, 3, 64).
// ---------------------------------------------------------------------------
__global__ void __launch_bounds__(256, 2)
disent_kernel(int which)
{
    const int i0 = blockIdx.y * 128;           // row block base (i or j)
    const int t0 = blockIdx.x * 128;
    const int r_max = (i0 + 127 < KS - 1) ? i0 + 127 : KS - 1;
    int t_lo, t_hi;
    if (which == 0) { t_lo = (KS - 1) - r_max;  t_hi = (2*KS - 2) - i0; }
    else            { t_lo = i0;                t_hi = r_max + (KS - 1); }
    if (t0 > t_hi || t0 + 127 < t_lo) return;  // tile never read

    __shared__ float As[16*PAD], Bs[16*PAD];
    const int bh = blockIdx.z;
    const int h  = bh & 7;
    const float* vecs = which ? g_k  : g_q;
    const float* pos  = which ? g_pq : g_pk;
    float*       out  = which ? g_p2c : g_c2p;

    float acc[8][8] = {};
    sgemm128_core(vecs + (size_t)bh*KS*KD, KD, i0, KS,
                  pos  + (size_t)h*KT*KD,  KD, t0, KT, KD, acc, As, Bs);

    const int tx = threadIdx.x & 15, ty = threadIdx.x >> 4;
    #pragma unroll
    for (int r = 0; r < 8; r++) {
        const int i = i0 + ty*8 + r;
        float* orow = out + ((size_t)bh*KS + i)*KTP + t0 + tx*8;  // 16B aligned
        #pragma unroll
        for (int cc = 0; cc < 8; cc += 4) {
            float4 v = make_float4(acc[r][cc+0], acc[r][cc+1],
                                   acc[r][cc+2], acc[r][cc+3]);
            *(float4*)(orow + cc) = v;
        }
    }
}

// ---------------------------------------------------------------------------
// 64x64 tile core used inside the attention kernel.
// ---------------------------------------------------------------------------
__device__ __forceinline__ void sgemm64_core(
    const float* __restrict__ A, int lda, int a0, int Mlim,
    const float* __restrict__ Bm, int ldb, int b0, int Nlim,
    int K, float acc[4][4], float* As, float* Bs)
{
    const int tid = threadIdx.x;
    const int tx = tid & 15, ty = tid >> 4;
    const int lr = tid >> 2;
    const int lk = (tid & 3) * 4;

    for (int k0 = 0; k0 < K; k0 += 16) {
        __syncthreads();
        {
            int row = a0 + lr;
            float4 v = make_float4(0.f, 0.f, 0.f, 0.f);
            if (row < Mlim)
                v = *(const float4*)(A + (size_t)row * lda + k0 + lk);
            As[(lk+0)*68 + lr] = v.x; As[(lk+1)*68 + lr] = v.y;
            As[(lk+2)*68 + lr] = v.z; As[(lk+3)*68 + lr] = v.w;
        }
        {
            int row = b0 + lr;
            float4 v = make_float4(0.f, 0.f, 0.f, 0.f);
            if (row < Nlim)
                v = *(const float4*)(Bm + (size_t)row * ldb + k0 + lk);
            Bs[(lk+0)*68 + lr] = v.x; Bs[(lk+1)*68 + lr] = v.y;
            Bs[(lk+2)*68 + lr] = v.z; Bs[(lk+3)*68 + lr] = v.w;
        }
        __syncthreads();
        #pragma unroll
        for (int kk = 0; kk < 16; kk++) {
            float4 a4 = *(const float4*)&As[kk*68 + ty*4];
            float4 b4 = *(const float4*)&Bs[kk*68 + tx*4];
            float av[4] = {a4.x, a4.y, a4.z, a4.w};
            float bv[4] = {b4.x, b4.y, b4.z, b4.w};
            #pragma unroll
            for (int r = 0; r < 4; r++)
                #pragma unroll
                for (int c = 0; c < 4; c++)
                    acc[r][c] = fmaf(av[r], bv[c], acc[r][c]);
        }
    }
}

// ---------------------------------------------------------------------------
// K5: flash attention per (i-tile=64, h, b).  Online softmax over 6 j-tiles.
// logits = (qk + c2p_gather + p2c_gather) * SCALE, mask fill -9e15.
// ---------------------------------------------------------------------------
__global__ void attn_kernel(const int* __restrict__ mask)
{
    __shared__ float As[16*68], Bs[16*68];
    __shared__ float Ss[64*65];
    __shared__ float Vs[64*68];          // aliased: p2c band stage, then V tile
    __shared__ float row_m[64], row_l[64], alpha_s[64];
    __shared__ float red[64*4];
    __shared__ int   msks[64];

    const int i0 = blockIdx.x * 64;
    const int h  = blockIdx.y;
    const int b  = blockIdx.z;
    const int bh = b*KH + h;
    const float* qb   = g_q + (size_t)bh*KS*KD;
    const float* kb   = g_k + (size_t)bh*KS*KD;
    const float* vb   = g_v + (size_t)bh*KS*KD;
    const float* c2pb = g_c2p + (size_t)bh*KS*KTP;
    const float* p2cb = g_p2c + (size_t)bh*KS*KTP;

    const int tid = threadIdx.x;
    const int tx = tid & 15, ty = tid >> 4;
    const int rrow = tid >> 2, q4 = tid & 3;   // softmax: 4 threads per row

    float o[4][4] = {};
    if (tid < 64) { row_m[tid] = -1e30f; row_l[tid] = 0.f; }

    for (int j0 = 0; j0 < KS; j0 += 64) {
        // ---- stage p2c diagonal band into Vs (coalesced per j-row) ----
        __syncthreads();
        {
            const int c = rrow;                     // local j
            const int j = j0 + c;
            const float* src = p2cb + (size_t)j*KTP + (j - i0 + 320);
            #pragma unroll
            for (int xx = 0; xx < 16; xx++) {
                const int x = q4 + xx*4;
                Vs[c*68 + x] = src[x];              // t = j-i0+320+x ; x = 63-r
            }
        }
        if (tid < 64) msks[tid] = mask[b*KS + j0 + tid];
        __syncthreads();

        // ---- init acc with c2p (gmem gather) + p2c (staged) ----
        float acc[4][4];
        #pragma unroll
        for (int r = 0; r < 4; r++) {
            const int i = i0 + ty*4 + r;
            const float* crow = c2pb + (size_t)i*KTP + (j0 - i + 383);
            #pragma unroll
            for (int c = 0; c < 4; c++) {
                const int jl = tx*4 + c;
                acc[r][c] = crow[jl] + Vs[jl*68 + 63 - (ty*4 + r)];
            }
        }

        // ---- c2c: q @ k^T ----
        sgemm64_core(qb, KD, i0, KS, kb, KD, j0, KS, KD, acc, As, Bs);

        // ---- scale + mask, write S tile ----
        #pragma unroll
        for (int r = 0; r < 4; r++)
            #pragma unroll
            for (int c = 0; c < 4; c++) {
                float v = acc[r][c] * KSCALE;
                if (msks[tx*4 + c] == 0) v = -9e15f;
                Ss[(ty*4 + r)*65 + tx*4 + c] = v;
            }
        __syncthreads();

        // ---- online softmax (4 threads/row) ----
        {
            float mx = -1e30f;
            #pragma unroll
            for (int jj = q4*16; jj < q4*16 + 16; jj++)
                mx = fmaxf(mx, Ss[rrow*65 + jj]);
            red[rrow*4 + q4] = mx;
        }
        __syncthreads();
        if (q4 == 0) {
            float mn = fmaxf(fmaxf(red[rrow*4+0], red[rrow*4+1]),
                             fmaxf(red[rrow*4+2], red[rrow*4+3]));
            mn = fmaxf(mn, row_m[rrow]);
            alpha_s[rrow] = __expf(row_m[rrow] - mn);
            row_m[rrow] = mn;
        }
        __syncthreads();
        {
            const float mn = row_m[rrow];
            float s = 0.f;
            #pragma unroll
            for (int jj = q4*16; jj < q4*16 + 16; jj++) {
                float p = __expf(Ss[rrow*65 + jj] - mn);
                Ss[rrow*65 + jj] = p;
                s += p;
            }
            red[rrow*4 + q4] = s;
        }
        __syncthreads();
        if (q4 == 0)
            row_l[rrow] = row_l[rrow]*alpha_s[rrow]
                        + red[rrow*4+0] + red[rrow*4+1] + red[rrow*4+2] + red[rrow*4+3];

        // ---- load V tile into Vs (band consumed already) ----
        {
            const int c = rrow, d0 = q4 * 16;
            const float* src = vb + (size_t)(j0 + c)*KD + d0;
            #pragma unroll
            for (int dd = 0; dd < 16; dd += 4)
                *(float4*)&Vs[c*68 + d0 + dd] = *(const float4*)(src + dd);
        }
        __syncthreads();

        // ---- rescale O, accumulate P @ V ----
        float al[4];
        #pragma unroll
        for (int r = 0; r < 4; r++) al[r] = alpha_s[ty*4 + r];
        #pragma unroll
        for (int r = 0; r < 4; r++)
            #pragma unroll
            for (int c = 0; c < 4; c++) o[r][c] *= al[r];

        #pragma unroll
        for (int jj = 0; jj < 64; jj++) {
            float pv[4];
            #pragma unroll
            for (int r = 0; r < 4; r++) pv[r] = Ss[(ty*4 + r)*65 + jj];
            float4 vv = *(const float4*)&Vs[jj*68 + tx*4];
            float vvv[4] = {vv.x, vv.y, vv.z, vv.w};
            #pragma unroll
            for (int r = 0; r < 4; r++)
                #pragma unroll
                for (int c = 0; c < 4; c++)
                    o[r][c] = fmaf(pv[r], vvv[c], o[r][c]);
        }
    }

    // ---- normalize, store ctx [b][s][h*D+d] ----
    float inv[4];
    #pragma unroll
    for (int r = 0; r < 4; r++) inv[r] = 1.f / row_l[ty*4 + r];
    #pragma unroll
    for (int r = 0; r < 4; r++) {
        const int i = i0 + ty*4 + r;
        #pragma unroll
        for (int c = 0; c < 4; c++)
            g_ctx[((size_t)b*KS + i)*KE + h*KD + tx*4 + c] = o[r][c] * inv[r];
    }
}

// ---------------------------------------------------------------------------
// K6: output projection: out = ctx @ Wo^T + bo
// grid (512/128=4, 3072/128=24).
// ---------------------------------------------------------------------------
__global__ void __launch_bounds__(256, 2)
out_kernel(const float* __restrict__ Wo, const float* __restrict__ bo,
           float* __restrict__ out)
{
    __shared__ float As[16*PAD], Bs[16*PAD];
    const int m0 = blockIdx.y * 128;
    const int n0 = blockIdx.x * 128;

    float acc[8][8] = {};
    sgemm128_core(g_ctx, KE, m0, KB*KS, Wo, KE, n0, KIN, KE, acc, As, Bs);

    const int tx = threadIdx.x & 15, ty = threadIdx.x >> 4;
    #pragma unroll
    for (int r = 0; r < 8; r++) {
        const int m = m0 + ty*8 + r;
        float* orow = out + (size_t)m*KIN + n0 + tx*8;
        #pragma unroll
        for (int cc = 0; cc < 8; cc += 4) {
            const int n = n0 + tx*8 + cc;
            float4 v;
            v.x = acc[r][cc+0] + bo[n+0];
            v.y = acc[r][cc+1] + bo[n+1];
            v.z = acc[r][cc+2] + bo[n+2];
            v.w = acc[r][cc+3] + bo[n+3];
            *(float4*)(orow + cc) = v;
        }
    }
}

// ---------------------------------------------------------------------------
extern "C" void kernel_launch(void* const* d_in, const int* in_sizes, int n_in,
                              void* d_out, int out_size)
{
    const float* x    = (const float*)d_in[0];
    const int*   mask = (const int*)  d_in[1];
    const float* Wq   = (const float*)d_in[2];
    const float* bq   = (const float*)d_in[3];
    const float* Wk   = (const float*)d_in[4];
    const float* bk   = (const float*)d_in[5];
    const float* Wv   = (const float*)d_in[6];
    const float* bv   = (const float*)d_in[7];
    const float* rel  = (const float*)d_in[8];
    const float* Wpk  = (const float*)d_in[9];
    const float* bpk  = (const float*)d_in[10];
    const float* Wpq  = (const float*)d_in[11];
    const float* bpq  = (const float*)d_in[12];
    const float* Wo   = (const float*)d_in[13];
    const float* bo   = (const float*)d_in[14];

    dim3 thr(256);
    qkv_kernel   <<<dim3(1536/128, (KB*KS)/128), thr>>>(x, Wq, bq, Wk, bk, Wv, bv);
    pos_kernel   <<<dim3(1024/128, (KT + 127)/128), thr>>>(rel, Wpk, bpk, Wpq, bpq);
    disent_kernel<<<dim3((KT + 127)/128, KS/128, KB*KH), thr>>>(0);
    disent_kernel<<<dim3((KT + 127)/128, KS/128, KB*KH), thr>>>(1);
    attn_kernel  <<<dim3(KS/64, KH, KB), thr>>>(mask);
    out_kernel   <<<dim3(KIN/128, (KB*KS)/128), thr>>>(Wo, bo, (float*)d_out);
}

// round 7
// speedup vs baseline: 1.9840x; 1.7448x over previous
#include <cuda_runtime.h>

// ---------------------------------------------------------------------------
// DeBERTa-style disentangled attention, fp32.
// B=8 S=384 IN=512 E=512 H=8 D=64, rel offsets t in [0,767), table row t+128.
// R7: conflict-free strided fragments (rows ty*4/64+ty*4, cols tx*4/64+tx*4),
//     BK=32, coalesced loader. Fixes 4-way LDS conflicts on B fragments.
// ---------------------------------------------------------------------------

#define KB 8
#define KS 384
#define KIN 512
#define KE 512
#define KH 8
#define KD 64
#define KT 767            // 2*S-1 (logical)
#define KTP 768           // padded row stride for c2p/p2c scratch
#define KRELOFF 128       // table row = t + 128
#define KSCALE 0.07216878364870323f   // 1/sqrt(64*3)

#define PAD 132           // smem row stride (floats) for 128-wide k-planes

__device__ float g_q[KB*KH*KS*KD];
__device__ float g_k[KB*KH*KS*KD];
__device__ float g_v[KB*KH*KS*KD];
__device__ float g_pk[KH*KT*KD];
__device__ float g_pq[KH*KT*KD];
__device__ float g_c2p[(size_t)KB*KH*KS*KTP];
__device__ float g_p2c[(size_t)KB*KH*KS*KTP];
__device__ float g_ctx[KB*KS*KE];

// ---------------------------------------------------------------------------
// 128x128 tile fp32 GEMM core, 256 threads, BK=32.
// Thread (tx,ty) owns rows {ty*4+r, 64+ty*4+r} x cols {tx*4+c, 64+tx*4+c}:
//   acc[rh][ch][r][c] += sum_k A[a0+rh*64+ty*4+r][k] * Bm[b0+ch*64+tx*4+c][k]
// Fragment LDS: A-side broadcast, B-side 16B-stride contiguous -> conflict-free.
// As/Bs: 32*PAD floats each (caller-provided smem). K must be a multiple of 32.
// ---------------------------------------------------------------------------
__device__ __forceinline__ void sgemm128_core(
    const float* __restrict__ A, int lda, int a0, int Mlim,
    const float* __restrict__ Bm, int ldb, int b0, int Nlim,
    int K, float acc[2][2][4][4], float* As, float* Bs)
{
    const int tid = threadIdx.x;
    const int tx = tid & 15, ty = tid >> 4;
    const int lrow = tid >> 3;         // 0..31
    const int lk = (tid & 7) * 4;      // 0,4,...,28

    for (int k0 = 0; k0 < K; k0 += 32) {
        __syncthreads();
        #pragma unroll
        for (int h4 = 0; h4 < 4; h4++) {
            const int row = lrow + h4 * 32;
            {
                const int ar = a0 + row;
                float4 v = make_float4(0.f, 0.f, 0.f, 0.f);
                if (ar < Mlim)
                    v = *(const float4*)(A + (size_t)ar * lda + k0 + lk);
                As[(lk+0)*PAD + row] = v.x; As[(lk+1)*PAD + row] = v.y;
                As[(lk+2)*PAD + row] = v.z; As[(lk+3)*PAD + row] = v.w;
            }
            {
                const int br = b0 + row;
                float4 v = make_float4(0.f, 0.f, 0.f, 0.f);
                if (br < Nlim)
                    v = *(const float4*)(Bm + (size_t)br * ldb + k0 + lk);
                Bs[(lk+0)*PAD + row] = v.x; Bs[(lk+1)*PAD + row] = v.y;
                Bs[(lk+2)*PAD + row] = v.z; Bs[(lk+3)*PAD + row] = v.w;
            }
        }
        __syncthreads();
        #pragma unroll 8
        for (int kk = 0; kk < 32; kk++) {
            float a8[8], b8[8];
            *(float4*)&a8[0] = *(const float4*)&As[kk*PAD + ty*4];
            *(float4*)&a8[4] = *(const float4*)&As[kk*PAD + 64 + ty*4];
            *(float4*)&b8[0] = *(const float4*)&Bs[kk*PAD + tx*4];
            *(float4*)&b8[4] = *(const float4*)&Bs[kk*PAD + 64 + tx*4];
            #pragma unroll
            for (int rh = 0; rh < 2; rh++)
                #pragma unroll
                for (int r = 0; r < 4; r++)
                    #pragma unroll
                    for (int ch = 0; ch < 2; ch++)
                        #pragma unroll
                        for (int c = 0; c < 4; c++)
                            acc[rh][ch][r][c] =
                                fmaf(a8[rh*4+r], b8[ch*4+c], acc[rh][ch][r][c]);
        }
    }
}

// ---------------------------------------------------------------------------
// K1: fused QKV projection.  out[m][n] = x[m] . W[n] + b[n]
// grid (1536/128=12, 3072/128=24); each N-tile lies inside one of Wq/Wk/Wv.
// ---------------------------------------------------------------------------
__global__ void __launch_bounds__(256, 2)
qkv_kernel(const float* __restrict__ x,
           const float* __restrict__ Wq, const float* __restrict__ bq,
           const float* __restrict__ Wk, const float* __restrict__ bk,
           const float* __restrict__ Wv, const float* __restrict__ bv)
{
    __shared__ float As[32*PAD], Bs[32*PAD];
    const int m0 = blockIdx.y * 128;
    const int n0 = blockIdx.x * 128;
    const int which = n0 >> 9;
    const float* W    = (which == 0) ? Wq : (which == 1) ? Wk : Wv;
    const float* bias = (which == 0) ? bq : (which == 1) ? bk : bv;
    float* dst        = (which == 0) ? g_q : (which == 1) ? g_k : g_v;
    const int e0 = n0 & 511;

    float acc[2][2][4][4] = {};
    sgemm128_core(x, KIN, m0, KB*KS, W, KIN, e0, KE, KIN, acc, As, Bs);

    const int tx = threadIdx.x & 15, ty = threadIdx.x >> 4;
    #pragma unroll
    for (int rh = 0; rh < 2; rh++)
        #pragma unroll
        for (int r = 0; r < 4; r++) {
            const int m = m0 + rh*64 + ty*4 + r;
            const int b = m / KS, s = m % KS;
            #pragma unroll
            for (int ch = 0; ch < 2; ch++) {
                const int ebase = e0 + ch*64 + tx*4;
                const int h = ebase >> 6, d0 = ebase & 63;
                float4 v;
                v.x = acc[rh][ch][r][0] + bias[ebase+0];
                v.y = acc[rh][ch][r][1] + bias[ebase+1];
                v.z = acc[rh][ch][r][2] + bias[ebase+2];
                v.w = acc[rh][ch][r][3] + bias[ebase+3];
                *(float4*)(dst + ((size_t)(b*KH + h)*KS + s)*KD + d0) = v;
            }
        }
}

// ---------------------------------------------------------------------------
// K2: positional projections PK[t] / PQ[t], t in [0,767).
// grid (1024/128=8, ceil(767/128)=6).
// ---------------------------------------------------------------------------
__global__ void __launch_bounds__(256, 2)
pos_kernel(const float* __restrict__ rel_table,
           const float* __restrict__ Wpk, const float* __restrict__ bpk,
           const float* __restrict__ Wpq, const float* __restrict__ bpq)
{
    __shared__ float As[32*PAD], Bs[32*PAD];
    const int m0 = blockIdx.y * 128;
    const int n0 = blockIdx.x * 128;
    const bool isq = (n0 >= 512);
    const float* W    = isq ? Wpq : Wpk;
    const float* bias = isq ? bpq : bpk;
    float* dst        = isq ? g_pq : g_pk;
    const int e0 = n0 & 511;

    float acc[2][2][4][4] = {};
    sgemm128_core(rel_table + (size_t)KRELOFF*KIN, KIN, m0, KT,
                  W, KIN, e0, KE, KIN, acc, As, Bs);

    const int tx = threadIdx.x & 15, ty = threadIdx.x >> 4;
    #pragma unroll
    for (int rh = 0; rh < 2; rh++)
        #pragma unroll
        for (int r = 0; r < 4; r++) {
            const int t = m0 + rh*64 + ty*4 + r;
            if (t >= KT) continue;
            #pragma unroll
            for (int ch = 0; ch < 2; ch++) {
                const int ebase = e0 + ch*64 + tx*4;
                const int h = ebase >> 6, d0 = ebase & 63;
                float4 v;
                v.x = acc[rh][ch][r][0] + bias[ebase+0];
                v.y = acc[rh][ch][r][1] + bias[ebase+1];
                v.z = acc[rh][ch][r][2] + bias[ebase+2];
                v.w = acc[rh][ch][r][3] + bias[ebase+3];
                *(float4*)(dst + ((size_t)h*KT + t)*KD + d0) = v;
            }
        }
}

// ---------------------------------------------------------------------------
// K3/K4: disentangled score tables with t-window tile skipping.
//   which==0: C2P[bh][i][t] = q[bh][i] . PK[h][t]   window [383-r_max, 766-i0]
//   which==1: P2C[bh][j][t] = k[bh][j] . PQ[h][t]   window [i0, r_max+383]
// Scratch row stride KTP=768 -> all float4 stores 16B aligned.
// grid (6, 3, 64).
// ---------------------------------------------------------------------------
__global__ void __launch_bounds__(256, 2)
disent_kernel(int which)
{
    const int i0 = blockIdx.y * 128;           // row block base (i or j)
    const int t0 = blockIdx.x * 128;
    const int r_max = (i0 + 127 < KS - 1) ? i0 + 127 : KS - 1;
    int t_lo, t_hi;
    if (which == 0) { t_lo = (KS - 1) - r_max;  t_hi = (2*KS - 2) - i0; }
    else            { t_lo = i0;                t_hi = r_max + (KS - 1); }
    if (t0 > t_hi || t0 + 127 < t_lo) return;  // tile never read

    __shared__ float As[32*PAD], Bs[32*PAD];
    const int bh = blockIdx.z;
    const int h  = bh & 7;
    const float* vecs = which ? g_k  : g_q;
    const float* pos  = which ? g_pq : g_pk;
    float*       out  = which ? g_p2c : g_c2p;

    float acc[2][2][4][4] = {};
    sgemm128_core(vecs + (size_t)bh*KS*KD, KD, i0, KS,
                  pos  + (size_t)h*KT*KD,  KD, t0, KT, KD, acc, As, Bs);

    const int tx = threadIdx.x & 15, ty = threadIdx.x >> 4;
    #pragma unroll
    for (int rh = 0; rh < 2; rh++)
        #pragma unroll
        for (int r = 0; r < 4; r++) {
            const int i = i0 + rh*64 + ty*4 + r;
            float* orow = out + ((size_t)bh*KS + i)*KTP;
            #pragma unroll
            for (int ch = 0; ch < 2; ch++) {
                const int t = t0 + ch*64 + tx*4;
                float4 v = make_float4(acc[rh][ch][r][0], acc[rh][ch][r][1],
                                       acc[rh][ch][r][2], acc[rh][ch][r][3]);
                *(float4*)(orow + t) = v;       // t multiple of 4, KTP even
            }
        }
}

// ---------------------------------------------------------------------------
// 64x64 tile core used inside the attention kernel (16B-stride fragments,
// already conflict-free).
// ---------------------------------------------------------------------------
__device__ __forceinline__ void sgemm64_core(
    const float* __restrict__ A, int lda, int a0, int Mlim,
    const float* __restrict__ Bm, int ldb, int b0, int Nlim,
    int K, float acc[4][4], float* As, float* Bs)
{
    const int tid = threadIdx.x;
    const int tx = tid & 15, ty = tid >> 4;
    const int lr = tid >> 2;
    const int lk = (tid & 3) * 4;

    for (int k0 = 0; k0 < K; k0 += 16) {
        __syncthreads();
        {
            int row = a0 + lr;
            float4 v = make_float4(0.f, 0.f, 0.f, 0.f);
            if (row < Mlim)
                v = *(const float4*)(A + (size_t)row * lda + k0 + lk);
            As[(lk+0)*68 + lr] = v.x; As[(lk+1)*68 + lr] = v.y;
            As[(lk+2)*68 + lr] = v.z; As[(lk+3)*68 + lr] = v.w;
        }
        {
            int row = b0 + lr;
            float4 v = make_float4(0.f, 0.f, 0.f, 0.f);
            if (row < Nlim)
                v = *(const float4*)(Bm + (size_t)row * ldb + k0 + lk);
            Bs[(lk+0)*68 + lr] = v.x; Bs[(lk+1)*68 + lr] = v.y;
            Bs[(lk+2)*68 + lr] = v.z; Bs[(lk+3)*68 + lr] = v.w;
        }
        __syncthreads();
        #pragma unroll
        for (int kk = 0; kk < 16; kk++) {
            float4 a4 = *(const float4*)&As[kk*68 + ty*4];
            float4 b4 = *(const float4*)&Bs[kk*68 + tx*4];
            float av[4] = {a4.x, a4.y, a4.z, a4.w};
            float bv[4] = {b4.x, b4.y, b4.z, b4.w};
            #pragma unroll
            for (int r = 0; r < 4; r++)
                #pragma unroll
                for (int c = 0; c < 4; c++)
                    acc[r][c] = fmaf(av[r], bv[c], acc[r][c]);
        }
    }
}

// ---------------------------------------------------------------------------
// K5: flash attention per (i-tile=64, h, b).  Online softmax over 6 j-tiles.
// logits = (qk + c2p_gather + p2c_gather) * SCALE, mask fill -9e15.
// ---------------------------------------------------------------------------
__global__ void attn_kernel(const int* __restrict__ mask)
{
    __shared__ float As[16*68], Bs[16*68];
    __shared__ float Ss[64*65];
    __shared__ float Vs[64*68];          // aliased: p2c band stage, then V tile
    __shared__ float row_m[64], row_l[64], alpha_s[64];
    __shared__ float red[64*4];
    __shared__ int   msks[64];

    const int i0 = blockIdx.x * 64;
    const int h  = blockIdx.y;
    const int b  = blockIdx.z;
    const int bh = b*KH + h;
    const float* qb   = g_q + (size_t)bh*KS*KD;
    const float* kb   = g_k + (size_t)bh*KS*KD;
    const float* vb   = g_v + (size_t)bh*KS*KD;
    const float* c2pb = g_c2p + (size_t)bh*KS*KTP;
    const float* p2cb = g_p2c + (size_t)bh*KS*KTP;

    const int tid = threadIdx.x;
    const int tx = tid & 15, ty = tid >> 4;
    const int rrow = tid >> 2, q4 = tid & 3;   // softmax: 4 threads per row

    float o[4][4] = {};
    if (tid < 64) { row_m[tid] = -1e30f; row_l[tid] = 0.f; }

    for (int j0 = 0; j0 < KS; j0 += 64) {
        // ---- stage p2c diagonal band into Vs (coalesced per j-row) ----
        __syncthreads();
        {
            const int c = rrow;                     // local j
            const int j = j0 + c;
            const float* src = p2cb + (size_t)j*KTP + (j - i0 + 320);
            #pragma unroll
            for (int xx = 0; xx < 16; xx++) {
                const int x = q4 + xx*4;
                Vs[c*68 + x] = src[x];              // t = j-i0+320+x ; x = 63-r
            }
        }
        if (tid < 64) msks[tid] = mask[b*KS + j0 + tid];
        __syncthreads();

        // ---- init acc with c2p (gmem gather) + p2c (staged) ----
        float acc[4][4];
        #pragma unroll
        for (int r = 0; r < 4; r++) {
            const int i = i0 + ty*4 + r;
            const float* crow = c2pb + (size_t)i*KTP + (j0 - i + 383);
            #pragma unroll
            for (int c = 0; c < 4; c++) {
                const int jl = tx*4 + c;
                acc[r][c] = crow[jl] + Vs[jl*68 + 63 - (ty*4 + r)];
            }
        }

        // ---- c2c: q @ k^T ----
        sgemm64_core(qb, KD, i0, KS, kb, KD, j0, KS, KD, acc, As, Bs);

        // ---- scale + mask, write S tile ----
        #pragma unroll
        for (int r = 0; r < 4; r++)
            #pragma unroll
            for (int c = 0; c < 4; c++) {
                float v = acc[r][c] * KSCALE;
                if (msks[tx*4 + c] == 0) v = -9e15f;
                Ss[(ty*4 + r)*65 + tx*4 + c] = v;
            }
        __syncthreads();

        // ---- online softmax (4 threads/row) ----
        {
            float mx = -1e30f;
            #pragma unroll
            for (int jj = q4*16; jj < q4*16 + 16; jj++)
                mx = fmaxf(mx, Ss[rrow*65 + jj]);
            red[rrow*4 + q4] = mx;
        }
        __syncthreads();
        if (q4 == 0) {
            float mn = fmaxf(fmaxf(red[rrow*4+0], red[rrow*4+1]),
                             fmaxf(red[rrow*4+2], red[rrow*4+3]));
            mn = fmaxf(mn, row_m[rrow]);
            alpha_s[rrow] = __expf(row_m[rrow] - mn);
            row_m[rrow] = mn;
        }
        __syncthreads();
        {
            const float mn = row_m[rrow];
            float s = 0.f;
            #pragma unroll
            for (int jj = q4*16; jj < q4*16 + 16; jj++) {
                float p = __expf(Ss[rrow*65 + jj] - mn);
                Ss[rrow*65 + jj] = p;
                s += p;
            }
            red[rrow*4 + q4] = s;
        }
        __syncthreads();
        if (q4 == 0)
            row_l[rrow] = row_l[rrow]*alpha_s[rrow]
                        + red[rrow*4+0] + red[rrow*4+1] + red[rrow*4+2] + red[rrow*4+3];

        // ---- load V tile into Vs (band consumed already) ----
        {
            const int c = rrow, d0 = q4 * 16;
            const float* src = vb + (size_t)(j0 + c)*KD + d0;
            #pragma unroll
            for (int dd = 0; dd < 16; dd += 4)
                *(float4*)&Vs[c*68 + d0 + dd] = *(const float4*)(src + dd);
        }
        __syncthreads();

        // ---- rescale O, accumulate P @ V ----
        float al[4];
        #pragma unroll
        for (int r = 0; r < 4; r++) al[r] = alpha_s[ty*4 + r];
        #pragma unroll
        for (int r = 0; r < 4; r++)
            #pragma unroll
            for (int c = 0; c < 4; c++) o[r][c] *= al[r];

        #pragma unroll
        for (int jj = 0; jj < 64; jj++) {
            float pv[4];
            #pragma unroll
            for (int r = 0; r < 4; r++) pv[r] = Ss[(ty*4 + r)*65 + jj];
            float4 vv = *(const float4*)&Vs[jj*68 + tx*4];
            float vvv[4] = {vv.x, vv.y, vv.z, vv.w};
            #pragma unroll
            for (int r = 0; r < 4; r++)
                #pragma unroll
                for (int c = 0; c < 4; c++)
                    o[r][c] = fmaf(pv[r], vvv[c], o[r][c]);
        }
    }

    // ---- normalize, store ctx [b][s][h*D+d] ----
    float inv[4];
    #pragma unroll
    for (int r = 0; r < 4; r++) inv[r] = 1.f / row_l[ty*4 + r];
    #pragma unroll
    for (int r = 0; r < 4; r++) {
        const int i = i0 + ty*4 + r;
        #pragma unroll
        for (int c = 0; c < 4; c++)
            g_ctx[((size_t)b*KS + i)*KE + h*KD + tx*4 + c] = o[r][c] * inv[r];
    }
}

// ---------------------------------------------------------------------------
// K6: output projection: out = ctx @ Wo^T + bo
// grid (512/128=4, 3072/128=24).
// ---------------------------------------------------------------------------
__global__ void __launch_bounds__(256, 2)
out_kernel(const float* __restrict__ Wo, const float* __restrict__ bo,
           float* __restrict__ out)
{
    __shared__ float As[32*PAD], Bs[32*PAD];
    const int m0 = blockIdx.y * 128;
    const int n0 = blockIdx.x * 128;

    float acc[2][2][4][4] = {};
    sgemm128_core(g_ctx, KE, m0, KB*KS, Wo, KE, n0, KIN, KE, acc, As, Bs);

    const int tx = threadIdx.x & 15, ty = threadIdx.x >> 4;
    #pragma unroll
    for (int rh = 0; rh < 2; rh++)
        #pragma unroll
        for (int r = 0; r < 4; r++) {
            const int m = m0 + rh*64 + ty*4 + r;
            #pragma unroll
            for (int ch = 0; ch < 2; ch++) {
                const int n = n0 + ch*64 + tx*4;
                float4 v;
                v.x = acc[rh][ch][r][0] + bo[n+0];
                v.y = acc[rh][ch][r][1] + bo[n+1];
                v.z = acc[rh][ch][r][2] + bo[n+2];
                v.w = acc[rh][ch][r][3] + bo[n+3];
                *(float4*)(out + (size_t)m*KIN + n) = v;
            }
        }
}

// ---------------------------------------------------------------------------
extern "C" void kernel_launch(void* const* d_in, const int* in_sizes, int n_in,
                              void* d_out, int out_size)
{
    const float* x    = (const float*)d_in[0];
    const int*   mask = (const int*)  d_in[1];
    const float* Wq   = (const float*)d_in[2];
    const float* bq   = (const float*)d_in[3];
    const float* Wk   = (const float*)d_in[4];
    const float* bk   = (const float*)d_in[5];
    const float* Wv   = (const float*)d_in[6];
    const float* bv   = (const float*)d_in[7];
    const float* rel  = (const float*)d_in[8];
    const float* Wpk  = (const float*)d_in[9];
    const float* bpk  = (const float*)d_in[10];
    const float* Wpq  = (const float*)d_in[11];
    const float* bpq  = (const float*)d_in[12];
    const float* Wo   = (const float*)d_in[13];
    const float* bo   = (const float*)d_in[14];

    dim3 thr(256);
    qkv_kernel   <<<dim3(1536/128, (KB*KS)/128), thr>>>(x, Wq, bq, Wk, bk, Wv, bv);
    pos_kernel   <<<dim3(1024/128, (KT + 127)/128), thr>>>(rel, Wpk, bpk, Wpq, bpq);
    disent_kernel<<<dim3((KT + 127)/128, KS/128, KB*KH), thr>>>(0);
    disent_kernel<<<dim3((KT + 127)/128, KS/128, KB*KH), thr>>>(1);
    attn_kernel  <<<dim3(KS/64, KH, KB), thr>>>(mask);
    out_kernel   <<<dim3(KIN/128, (KB*KS)/128), thr>>>(Wo, bo, (float*)d_out);
}

// round 8
// speedup vs baseline: 2.0633x; 1.0400x over previous
#include <cuda_runtime.h>
#include <cstdint>

// ---------------------------------------------------------------------------
// DeBERTa-style disentangled attention.
// B=8 S=384 IN=512 E=512 H=8 D=64, rel offsets t in [0,767), table row t+128.
// R8: dense GEMMs (qkv/pos/disent/out) moved to tf32 mma.sync (m16n8k8) with
//     3xTF32 decomposition (hi/lo split) for fp32-class accuracy.
//     Attention kernel unchanged (scalar fp32 flash).
// ---------------------------------------------------------------------------

#define KB 8
#define KS 384
#define KIN 512
#define KE 512
#define KH 8
#define KD 64
#define KT 767            // 2*S-1 (logical)
#define KTP 768           // padded row stride for c2p/p2c scratch
#define KRELOFF 128       // table row = t + 128
#define KSCALE 0.07216878364870323f   // 1/sqrt(64*3)

#define PAD 132           // smem row stride (floats); 132%32=4 -> frag LDS conflict-free

__device__ float g_q[KB*KH*KS*KD];
__device__ float g_k[KB*KH*KS*KD];
__device__ float g_v[KB*KH*KS*KD];
__device__ float g_pk[KH*KT*KD];
__device__ float g_pq[KH*KT*KD];
__device__ float g_c2p[(size_t)KB*KH*KS*KTP];
__device__ float g_p2c[(size_t)KB*KH*KS*KTP];
__device__ float g_ctx[KB*KS*KE];

// ---------------------------------------------------------------------------
// tf32 helpers
// ---------------------------------------------------------------------------
__device__ __forceinline__ void split_tf32(float x, uint32_t& hi, uint32_t& lo)
{
    uint32_t h, l;
    asm("cvt.rna.tf32.f32 %0, %1;" : "=r"(h) : "f"(x));
    float lf = x - __uint_as_float(h);
    asm("cvt.rna.tf32.f32 %0, %1;" : "=r"(l) : "f"(lf));
    hi = h; lo = l;
}

__device__ __forceinline__ void mma_m16n8k8(float* d,
    uint32_t a0, uint32_t a1, uint32_t a2, uint32_t a3,
    uint32_t b0, uint32_t b1)
{
    asm("mma.sync.aligned.m16n8k8.row.col.f32.tf32.tf32.f32 "
        "{%0,%1,%2,%3}, {%4,%5,%6,%7}, {%8,%9}, {%0,%1,%2,%3};"
        : "+f"(d[0]), "+f"(d[1]), "+f"(d[2]), "+f"(d[3])
        : "r"(a0), "r"(a1), "r"(a2), "r"(a3), "r"(b0), "r"(b1));
}

// ---------------------------------------------------------------------------
// 128x128 tile GEMM core on tf32 tensor cores, 256 threads (8 warps), BK=32.
// Warp (wm,wn) = (warp>>2)*64, (warp&3)*32 owns a 64x32 sub-tile:
//   4 m-frags (m16) x 4 n-frags (n8), acc[mf][nf][4] fp32.
// C = A @ Bm^T with A:[Mlim x lda], Bm:[Nlim x ldb] row-major (k contiguous).
// 3xTF32: each operand split hi/lo; D += Ah*Bh + Ah*Bl + Al*Bh.
// As/Bs: 32*PAD floats each. K must be a multiple of 32.
//
// Fragment layout (PTX m16n8k8.row.col):
//   A: a0=(g, tig) a1=(g+8, tig) a2=(g, tig+4) a3=(g+8, tig+4)  [row, k]
//   B: b0=(tig, g) b1=(tig+4, g)                                 [k, col]
//   D: c0=(g, 2*tig) c1=(g, 2*tig+1) c2=(g+8, 2*tig) c3=(g+8, 2*tig+1)
// where g=lane>>2, tig=lane&3.
// ---------------------------------------------------------------------------
__device__ __forceinline__ void mma128_core(
    const float* __restrict__ A, int lda, int a0r, int Mlim,
    const float* __restrict__ Bm, int ldb, int b0r, int Nlim,
    int K, float acc[4][4][4], float* As, float* Bs)
{
    const int tid = threadIdx.x;
    const int lane = tid & 31, warp = tid >> 5;
    const int wm = (warp >> 2) * 64;
    const int wn = (warp & 3) * 32;
    const int g = lane >> 2, tig = lane & 3;
    const int lrow = tid >> 3;         // 0..31
    const int lk = (tid & 7) * 4;      // 0,4,...,28

    for (int k0 = 0; k0 < K; k0 += 32) {
        __syncthreads();
        #pragma unroll
        for (int h4 = 0; h4 < 4; h4++) {
            const int row = lrow + h4 * 32;
            {
                const int ar = a0r + row;
                float4 v = make_float4(0.f, 0.f, 0.f, 0.f);
                if (ar < Mlim)
                    v = *(const float4*)(A + (size_t)ar * lda + k0 + lk);
                As[(lk+0)*PAD + row] = v.x; As[(lk+1)*PAD + row] = v.y;
                As[(lk+2)*PAD + row] = v.z; As[(lk+3)*PAD + row] = v.w;
            }
            {
                const int br = b0r + row;
                float4 v = make_float4(0.f, 0.f, 0.f, 0.f);
                if (br < Nlim)
                    v = *(const float4*)(Bm + (size_t)br * ldb + k0 + lk);
                Bs[(lk+0)*PAD + row] = v.x; Bs[(lk+1)*PAD + row] = v.y;
                Bs[(lk+2)*PAD + row] = v.z; Bs[(lk+3)*PAD + row] = v.w;
            }
        }
        __syncthreads();
        #pragma unroll
        for (int kk = 0; kk < 32; kk += 8) {
            uint32_t bh[4][2], bl[4][2];
            #pragma unroll
            for (int nf = 0; nf < 4; nf++) {
                float b0f = Bs[(kk + tig)*PAD     + wn + nf*8 + g];
                float b1f = Bs[(kk + tig + 4)*PAD + wn + nf*8 + g];
                split_tf32(b0f, bh[nf][0], bl[nf][0]);
                split_tf32(b1f, bh[nf][1], bl[nf][1]);
            }
            #pragma unroll
            for (int mf = 0; mf < 4; mf++) {
                const int rb = wm + mf*16 + g;
                float a0f = As[(kk + tig)*PAD     + rb];
                float a1f = As[(kk + tig)*PAD     + rb + 8];
                float a2f = As[(kk + tig + 4)*PAD + rb];
                float a3f = As[(kk + tig + 4)*PAD + rb + 8];
                uint32_t ah[4], al[4];
                split_tf32(a0f, ah[0], al[0]);
                split_tf32(a1f, ah[1], al[1]);
                split_tf32(a2f, ah[2], al[2]);
                split_tf32(a3f, ah[3], al[3]);
                #pragma unroll
                for (int nf = 0; nf < 4; nf++) {
                    mma_m16n8k8(acc[mf][nf], ah[0],ah[1],ah[2],ah[3], bh[nf][0],bh[nf][1]);
                    mma_m16n8k8(acc[mf][nf], ah[0],ah[1],ah[2],ah[3], bl[nf][0],bl[nf][1]);
                    mma_m16n8k8(acc[mf][nf], al[0],al[1],al[2],al[3], bh[nf][0],bh[nf][1]);
                }
            }
        }
    }
}

// ---------------------------------------------------------------------------
// K1: fused QKV projection.  out[m][n] = x[m] . W[n] + b[n]
// grid (1536/128=12, 3072/128=24); each N-tile lies inside one of Wq/Wk/Wv.
// ---------------------------------------------------------------------------
__global__ void __launch_bounds__(256, 2)
qkv_kernel(const float* __restrict__ x,
           const float* __restrict__ Wq, const float* __restrict__ bq,
           const float* __restrict__ Wk, const float* __restrict__ bk,
           const float* __restrict__ Wv, const float* __restrict__ bv)
{
    __shared__ float As[32*PAD], Bs[32*PAD];
    const int m0 = blockIdx.y * 128;
    const int n0 = blockIdx.x * 128;
    const int which = n0 >> 9;
    const float* W    = (which == 0) ? Wq : (which == 1) ? Wk : Wv;
    const float* bias = (which == 0) ? bq : (which == 1) ? bk : bv;
    float* dst        = (which == 0) ? g_q : (which == 1) ? g_k : g_v;
    const int e0 = n0 & 511;

    float acc[4][4][4] = {};
    mma128_core(x, KIN, m0, KB*KS, W, KIN, e0, KE, KIN, acc, As, Bs);

    const int lane = threadIdx.x & 31, warp = threadIdx.x >> 5;
    const int wm = (warp >> 2) * 64, wn = (warp & 3) * 32;
    const int g = lane >> 2, tig = lane & 3;
    #pragma unroll
    for (int mf = 0; mf < 4; mf++)
        #pragma unroll
        for (int nf = 0; nf < 4; nf++) {
            const int e = e0 + wn + nf*8 + 2*tig;       // even
            const int h = e >> 6, d0 = e & 63;
            const float2 bv2 = make_float2(bias[e], bias[e+1]);
            #pragma unroll
            for (int half = 0; half < 2; half++) {
                const int m = m0 + wm + mf*16 + g + half*8;
                const int b = m / KS, s = m % KS;
                float2 v;
                v.x = acc[mf][nf][half*2+0] + bv2.x;
                v.y = acc[mf][nf][half*2+1] + bv2.y;
                *(float2*)(dst + ((size_t)(b*KH + h)*KS + s)*KD + d0) = v;
            }
        }
}

// ---------------------------------------------------------------------------
// K2: positional projections PK[t] / PQ[t], t in [0,767).
// grid (1024/128=8, 6).
// ---------------------------------------------------------------------------
__global__ void __launch_bounds__(256, 2)
pos_kernel(const float* __restrict__ rel_table,
           const float* __restrict__ Wpk, const float* __restrict__ bpk,
           const float* __restrict__ Wpq, const float* __restrict__ bpq)
{
    __shared__ float As[32*PAD], Bs[32*PAD];
    const int m0 = blockIdx.y * 128;
    const int n0 = blockIdx.x * 128;
    const bool isq = (n0 >= 512);
    const float* W    = isq ? Wpq : Wpk;
    const float* bias = isq ? bpq : bpk;
    float* dst        = isq ? g_pq : g_pk;
    const int e0 = n0 & 511;

    float acc[4][4][4] = {};
    mma128_core(rel_table + (size_t)KRELOFF*KIN, KIN, m0, KT,
                W, KIN, e0, KE, KIN, acc, As, Bs);

    const int lane = threadIdx.x & 31, warp = threadIdx.x >> 5;
    const int wm = (warp >> 2) * 64, wn = (warp & 3) * 32;
    const int g = lane >> 2, tig = lane & 3;
    #pragma unroll
    for (int mf = 0; mf < 4; mf++)
        #pragma unroll
        for (int nf = 0; nf < 4; nf++) {
            const int e = e0 + wn + nf*8 + 2*tig;
            const int h = e >> 6, d0 = e & 63;
            const float2 bv2 = make_float2(bias[e], bias[e+1]);
            #pragma unroll
            for (int half = 0; half < 2; half++) {
                const int t = m0 + wm + mf*16 + g + half*8;
                if (t >= KT) continue;
                float2 v;
                v.x = acc[mf][nf][half*2+0] + bv2.x;
                v.y = acc[mf][nf][half*2+1] + bv2.y;
                *(float2*)(dst + ((size_t)h*KT + t)*KD + d0) = v;
            }
        }
}

// ---------------------------------------------------------------------------
// K3/K4: disentangled score tables with t-window tile skipping.
//   which==0: C2P[bh][i][t] = q[bh][i] . PK[h][t]   window [383-r_max, 766-i0]
//   which==1: P2C[bh][j][t] = k[bh][j] . PQ[h][t]   window [i0, r_max+383]
// Scratch row stride KTP=768; col 767 may receive garbage (never read).
// grid (6, 3, 64).
// ---------------------------------------------------------------------------
__global__ void __launch_bounds__(256, 2)
disent_kernel(int which)
{
    const int i0 = blockIdx.y * 128;           // row block base (i or j)
    const int t0 = blockIdx.x * 128;
    const int r_max = (i0 + 127 < KS - 1) ? i0 + 127 : KS - 1;
    int t_lo, t_hi;
    if (which == 0) { t_lo = (KS - 1) - r_max;  t_hi = (2*KS - 2) - i0; }
    else            { t_lo = i0;                t_hi = r_max + (KS - 1); }
    if (t0 > t_hi || t0 + 127 < t_lo) return;  // tile never read

    __shared__ float As[32*PAD], Bs[32*PAD];
    const int bh = blockIdx.z;
    const int h  = bh & 7;
    const float* vecs = which ? g_k  : g_q;
    const float* pos  = which ? g_pq : g_pk;
    float*       out  = which ? g_p2c : g_c2p;

    float acc[4][4][4] = {};
    mma128_core(vecs + (size_t)bh*KS*KD, KD, i0, KS,
                pos  + (size_t)h*KT*KD,  KD, t0, KT, KD, acc, As, Bs);

    const int lane = threadIdx.x & 31, warp = threadIdx.x >> 5;
    const int wm = (warp >> 2) * 64, wn = (warp & 3) * 32;
    const int g = lane >> 2, tig = lane & 3;
    #pragma unroll
    for (int mf = 0; mf < 4; mf++)
        #pragma unroll
        for (int half = 0; half < 2; half++) {
            const int i = i0 + wm + mf*16 + g + half*8;
            float* orow = out + ((size_t)bh*KS + i)*KTP;
            #pragma unroll
            for (int nf = 0; nf < 4; nf++) {
                const int t = t0 + wn + nf*8 + 2*tig;   // even, < KTP
                float2 v;
                v.x = acc[mf][nf][half*2+0];
                v.y = acc[mf][nf][half*2+1];
                *(float2*)(orow + t) = v;
            }
        }
}

// ---------------------------------------------------------------------------
// 64x64 tile scalar core used inside the attention kernel.
// ---------------------------------------------------------------------------
__device__ __forceinline__ void sgemm64_core(
    const float* __restrict__ A, int lda, int a0, int Mlim,
    const float* __restrict__ Bm, int ldb, int b0, int Nlim,
    int K, float acc[4][4], float* As, float* Bs)
{
    const int tid = threadIdx.x;
    const int tx = tid & 15, ty = tid >> 4;
    const int lr = tid >> 2;
    const int lk = (tid & 3) * 4;

    for (int k0 = 0; k0 < K; k0 += 16) {
        __syncthreads();
        {
            int row = a0 + lr;
            float4 v = make_float4(0.f, 0.f, 0.f, 0.f);
            if (row < Mlim)
                v = *(const float4*)(A + (size_t)row * lda + k0 + lk);
            As[(lk+0)*68 + lr] = v.x; As[(lk+1)*68 + lr] = v.y;
            As[(lk+2)*68 + lr] = v.z; As[(lk+3)*68 + lr] = v.w;
        }
        {
            int row = b0 + lr;
            float4 v = make_float4(0.f, 0.f, 0.f, 0.f);
            if (row < Nlim)
                v = *(const float4*)(Bm + (size_t)row * ldb + k0 + lk);
            Bs[(lk+0)*68 + lr] = v.x; Bs[(lk+1)*68 + lr] = v.y;
            Bs[(lk+2)*68 + lr] = v.z; Bs[(lk+3)*68 + lr] = v.w;
        }
        __syncthreads();
        #pragma unroll
        for (int kk = 0; kk < 16; kk++) {
            float4 a4 = *(const float4*)&As[kk*68 + ty*4];
            float4 b4 = *(const float4*)&Bs[kk*68 + tx*4];
            float av[4] = {a4.x, a4.y, a4.z, a4.w};
            float bv[4] = {b4.x, b4.y, b4.z, b4.w};
            #pragma unroll
            for (int r = 0; r < 4; r++)
                #pragma unroll
                for (int c = 0; c < 4; c++)
                    acc[r][c] = fmaf(av[r], bv[c], acc[r][c]);
        }
    }
}

// ---------------------------------------------------------------------------
// K5: flash attention per (i-tile=64, h, b).  Online softmax over 6 j-tiles.
// logits = (qk + c2p_gather + p2c_gather) * SCALE, mask fill -9e15.
// ---------------------------------------------------------------------------
__global__ void attn_kernel(const int* __restrict__ mask)
{
    __shared__ float As[16*68], Bs[16*68];
    __shared__ float Ss[64*65];
    __shared__ float Vs[64*68];          // aliased: p2c band stage, then V tile
    __shared__ float row_m[64], row_l[64], alpha_s[64];
    __shared__ float red[64*4];
    __shared__ int   msks[64];

    const int i0 = blockIdx.x * 64;
    const int h  = blockIdx.y;
    const int b  = blockIdx.z;
    const int bh = b*KH + h;
    const float* qb   = g_q + (size_t)bh*KS*KD;
    const float* kb   = g_k + (size_t)bh*KS*KD;
    const float* vb   = g_v + (size_t)bh*KS*KD;
    const float* c2pb = g_c2p + (size_t)bh*KS*KTP;
    const float* p2cb = g_p2c + (size_t)bh*KS*KTP;

    const int tid = threadIdx.x;
    const int tx = tid & 15, ty = tid >> 4;
    const int rrow = tid >> 2, q4 = tid & 3;   // softmax: 4 threads per row

    float o[4][4] = {};
    if (tid < 64) { row_m[tid] = -1e30f; row_l[tid] = 0.f; }

    for (int j0 = 0; j0 < KS; j0 += 64) {
        // ---- stage p2c diagonal band into Vs (coalesced per j-row) ----
        __syncthreads();
        {
            const int c = rrow;                     // local j
            const int j = j0 + c;
            const float* src = p2cb + (size_t)j*KTP + (j - i0 + 320);
            #pragma unroll
            for (int xx = 0; xx < 16; xx++) {
                const int x = q4 + xx*4;
                Vs[c*68 + x] = src[x];              // t = j-i0+320+x ; x = 63-r
            }
        }
        if (tid < 64) msks[tid] = mask[b*KS + j0 + tid];
        __syncthreads();

        // ---- init acc with c2p (gmem gather) + p2c (staged) ----
        float acc[4][4];
        #pragma unroll
        for (int r = 0; r < 4; r++) {
            const int i = i0 + ty*4 + r;
            const float* crow = c2pb + (size_t)i*KTP + (j0 - i + 383);
            #pragma unroll
            for (int c = 0; c < 4; c++) {
                const int jl = tx*4 + c;
                acc[r][c] = crow[jl] + Vs[jl*68 + 63 - (ty*4 + r)];
            }
        }

        // ---- c2c: q @ k^T ----
        sgemm64_core(qb, KD, i0, KS, kb, KD, j0, KS, KD, acc, As, Bs);

        // ---- scale + mask, write S tile ----
        #pragma unroll
        for (int r = 0; r < 4; r++)
            #pragma unroll
            for (int c = 0; c < 4; c++) {
                float v = acc[r][c] * KSCALE;
                if (msks[tx*4 + c] == 0) v = -9e15f;
                Ss[(ty*4 + r)*65 + tx*4 + c] = v;
            }
        __syncthreads();

        // ---- online softmax (4 threads/row) ----
        {
            float mx = -1e30f;
            #pragma unroll
            for (int jj = q4*16; jj < q4*16 + 16; jj++)
                mx = fmaxf(mx, Ss[rrow*65 + jj]);
            red[rrow*4 + q4] = mx;
        }
        __syncthreads();
        if (q4 == 0) {
            float mn = fmaxf(fmaxf(red[rrow*4+0], red[rrow*4+1]),
                             fmaxf(red[rrow*4+2], red[rrow*4+3]));
            mn = fmaxf(mn, row_m[rrow]);
            alpha_s[rrow] = __expf(row_m[rrow] - mn);
            row_m[rrow] = mn;
        }
        __syncthreads();
        {
            const float mn = row_m[rrow];
            float s = 0.f;
            #pragma unroll
            for (int jj = q4*16; jj < q4*16 + 16; jj++) {
                float p = __expf(Ss[rrow*65 + jj] - mn);
                Ss[rrow*65 + jj] = p;
                s += p;
            }
            red[rrow*4 + q4] = s;
        }
        __syncthreads();
        if (q4 == 0)
            row_l[rrow] = row_l[rrow]*alpha_s[rrow]
                        + red[rrow*4+0] + red[rrow*4+1] + red[rrow*4+2] + red[rrow*4+3];

        // ---- load V tile into Vs (band consumed already) ----
        {
            const int c = rrow, d0 = q4 * 16;
            const float* src = vb + (size_t)(j0 + c)*KD + d0;
            #pragma unroll
            for (int dd = 0; dd < 16; dd += 4)
                *(float4*)&Vs[c*68 + d0 + dd] = *(const float4*)(src + dd);
        }
        __syncthreads();

        // ---- rescale O, accumulate P @ V ----
        float al[4];
        #pragma unroll
        for (int r = 0; r < 4; r++) al[r] = alpha_s[ty*4 + r];
        #pragma unroll
        for (int r = 0; r < 4; r++)
            #pragma unroll
            for (int c = 0; c < 4; c++) o[r][c] *= al[r];

        #pragma unroll
        for (int jj = 0; jj < 64; jj++) {
            float pv[4];
            #pragma unroll
            for (int r = 0; r < 4; r++) pv[r] = Ss[(ty*4 + r)*65 + jj];
            float4 vv = *(const float4*)&Vs[jj*68 + tx*4];
            float vvv[4] = {vv.x, vv.y, vv.z, vv.w};
            #pragma unroll
            for (int r = 0; r < 4; r++)
                #pragma unroll
                for (int c = 0; c < 4; c++)
                    o[r][c] = fmaf(pv[r], vvv[c], o[r][c]);
        }
    }

    // ---- normalize, store ctx [b][s][h*D+d] ----
    float inv[4];
    #pragma unroll
    for (int r = 0; r < 4; r++) inv[r] = 1.f / row_l[ty*4 + r];
    #pragma unroll
    for (int r = 0; r < 4; r++) {
        const int i = i0 + ty*4 + r;
        #pragma unroll
        for (int c = 0; c < 4; c++)
            g_ctx[((size_t)b*KS + i)*KE + h*KD + tx*4 + c] = o[r][c] * inv[r];
    }
}

// ---------------------------------------------------------------------------
// K6: output projection: out = ctx @ Wo^T + bo
// grid (512/128=4, 3072/128=24).
// ---------------------------------------------------------------------------
__global__ void __launch_bounds__(256, 2)
out_kernel(const float* __restrict__ Wo, const float* __restrict__ bo,
           float* __restrict__ out)
{
    __shared__ float As[32*PAD], Bs[32*PAD];
    const int m0 = blockIdx.y * 128;
    const int n0 = blockIdx.x * 128;

    float acc[4][4][4] = {};
    mma128_core(g_ctx, KE, m0, KB*KS, Wo, KE, n0, KIN, KE, acc, As, Bs);

    const int lane = threadIdx.x & 31, warp = threadIdx.x >> 5;
    const int wm = (warp >> 2) * 64, wn = (warp & 3) * 32;
    const int g = lane >> 2, tig = lane & 3;
    #pragma unroll
    for (int mf = 0; mf < 4; mf++)
        #pragma unroll
        for (int nf = 0; nf < 4; nf++) {
            const int n = n0 + wn + nf*8 + 2*tig;
            const float2 bv2 = make_float2(bo[n], bo[n+1]);
            #pragma unroll
            for (int half = 0; half < 2; half++) {
                const int m = m0 + wm + mf*16 + g + half*8;
                float2 v;
                v.x = acc[mf][nf][half*2+0] + bv2.x;
                v.y = acc[mf][nf][half*2+1] + bv2.y;
                *(float2*)(out + (size_t)m*KIN + n) = v;
            }
        }
}

// ---------------------------------------------------------------------------
extern "C" void kernel_launch(void* const* d_in, const int* in_sizes, int n_in,
                              void* d_out, int out_size)
{
    const float* x    = (const float*)d_in[0];
    const int*   mask = (const int*)  d_in[1];
    const float* Wq   = (const float*)d_in[2];
    const float* bq   = (const float*)d_in[3];
    const float* Wk   = (const float*)d_in[4];
    const float* bk   = (const float*)d_in[5];
    const float* Wv   = (const float*)d_in[6];
    const float* bv   = (const float*)d_in[7];
    const float* rel  = (const float*)d_in[8];
    const float* Wpk  = (const float*)d_in[9];
    const float* bpk  = (const float*)d_in[10];
    const float* Wpq  = (const float*)d_in[11];
    const float* bpq  = (const float*)d_in[12];
    const float* Wo   = (const float*)d_in[13];
    const float* bo   = (const float*)d_in[14];

    dim3 thr(256);
    qkv_kernel   <<<dim3(1536/128, (KB*KS)/128), thr>>>(x, Wq, bq, Wk, bk, Wv, bv);
    pos_kernel   <<<dim3(1024/128, (KT + 127)/128), thr>>>(rel, Wpk, bpk, Wpq, bpq);
    disent_kernel<<<dim3((KT + 127)/128, KS/128, KB*KH), thr>>>(0);
    disent_kernel<<<dim3((KT + 127)/128, KS/128, KB*KH), thr>>>(1);
    attn_kernel  <<<dim3(KS/64, KH, KB), thr>>>(mask);
    out_kernel   <<<dim3(KIN/128, (KB*KS)/128), thr>>>(Wo, bo, (float*)d_out);
}

// round 9
// speedup vs baseline: 2.8730x; 1.3924x over previous
#include <cuda_runtime.h>
#include <cuda_bf16.h>
#include <cstdint>

// ---------------------------------------------------------------------------
// DeBERTa-style disentangled attention.
// B=8 S=384 IN=512 E=512 H=8 D=64, rel offsets t in [0,767), table row t+128.
// R9: dense GEMMs on bf16 tensor cores (m16n8k16) with 3-term hi/lo split
//     (Ah*Bh + Ah*Bl + Al*Bh), splits computed ONCE in the tile loader and
//     stored in smem -> inner loop is pure LDS+MMA. Attention unchanged.
// ---------------------------------------------------------------------------

#define KB 8
#define KS 384
#define KIN 512
#define KE 512
#define KH 8
#define KD 64
#define KT 767            // 2*S-1 (logical)
#define KTP 768           // padded row stride for c2p/p2c scratch
#define KRELOFF 128       // table row = t + 128
#define KSCALE 0.07216878364870323f   // 1/sqrt(64*3)

#define BKP 40            // bf16 smem row stride (elems) = 80B -> frag LDS conflict-free

__device__ float g_q[KB*KH*KS*KD];
__device__ float g_k[KB*KH*KS*KD];
__device__ float g_v[KB*KH*KS*KD];
__device__ float g_pk[KH*KT*KD];
__device__ float g_pq[KH*KT*KD];
__device__ float g_c2p[(size_t)KB*KH*KS*KTP];
__device__ float g_p2c[(size_t)KB*KH*KS*KTP];
__device__ float g_ctx[KB*KS*KE];

// ---------------------------------------------------------------------------
// bf16 helpers
// ---------------------------------------------------------------------------
__device__ __forceinline__ void bsplit(float x, __nv_bfloat16& h, __nv_bfloat16& l)
{
    h = __float2bfloat16_rn(x);
    l = __float2bfloat16_rn(x - __bfloat162float(h));
}

__device__ __forceinline__ uint32_t pack2(__nv_bfloat16 a, __nv_bfloat16 b)
{
    __nv_bfloat162 t(a, b);          // .x = a (low half), .y = b (high half)
    return *reinterpret_cast<uint32_t*>(&t);
}

__device__ __forceinline__ void mma_bf16(float* d,
    uint32_t a0, uint32_t a1, uint32_t a2, uint32_t a3,
    uint32_t b0, uint32_t b1)
{
    asm("mma.sync.aligned.m16n8k16.row.col.f32.bf16.bf16.f32 "
        "{%0,%1,%2,%3}, {%4,%5,%6,%7}, {%8,%9}, {%0,%1,%2,%3};"
        : "+f"(d[0]), "+f"(d[1]), "+f"(d[2]), "+f"(d[3])
        : "r"(a0), "r"(a1), "r"(a2), "r"(a3), "r"(b0), "r"(b1));
}

// ---------------------------------------------------------------------------
// 128x128 tile GEMM core, 256 threads (8 warps), BK=32, bf16 3-term mma.
// C = A @ Bm^T, A:[Mlim x lda], Bm:[Nlim x ldb] row-major (k contiguous).
// Warp (warp>>2)*64 x (warp&3)*32 sub-tile: 4 m-frags (m16) x 4 n-frags (n8).
// Loader splits each f32 into bf16 hi/lo ONCE, stores [row][k] bf16 arrays
// (stride BKP=40 elems): frag LDS addr = row*20 + kk/2 + tig words -> all 32
// lanes hit distinct banks. K must be a multiple of 32.
//
// Fragment layout (m16n8k16.row.col, g=lane>>2, tig=lane&3):
//   A: a0=[g][2tig+kk] a1=[g+8][..] a2=[g][2tig+8+kk] a3=[g+8][..]
//   B: b0=[n=g][2tig+kk] b1=[n=g][2tig+8+kk]          (pairs packed in u32)
//   D: c0=(g,2tig) c1=(g,2tig+1) c2=(g+8,2tig) c3=(g+8,2tig+1)  [unchanged]
// ---------------------------------------------------------------------------
__device__ __forceinline__ void mma128_core(
    const float* __restrict__ A, int lda, int a0r, int Mlim,
    const float* __restrict__ Bm, int ldb, int b0r, int Nlim,
    int K, float acc[4][4][4],
    __nv_bfloat16* Ah, __nv_bfloat16* Al,
    __nv_bfloat16* Bh, __nv_bfloat16* Bl)
{
    const int tid = threadIdx.x;
    const int lane = tid & 31, warp = tid >> 5;
    const int wm = (warp >> 2) * 64;
    const int wn = (warp & 3) * 32;
    const int g = lane >> 2, tig = lane & 3;
    const int lrow = tid >> 3;         // 0..31
    const int lk = (tid & 7) * 4;      // 0,4,...,28

    for (int k0 = 0; k0 < K; k0 += 32) {
        __syncthreads();
        #pragma unroll
        for (int h4 = 0; h4 < 4; h4++) {
            const int row = lrow + h4 * 32;
            {
                const int ar = a0r + row;
                float4 v = make_float4(0.f, 0.f, 0.f, 0.f);
                if (ar < Mlim)
                    v = *(const float4*)(A + (size_t)ar * lda + k0 + lk);
                __nv_bfloat16 hx,hy,hz,hw, lx,ly,lz,lw;
                bsplit(v.x,hx,lx); bsplit(v.y,hy,ly);
                bsplit(v.z,hz,lz); bsplit(v.w,hw,lw);
                *(uint2*)&Ah[row*BKP + lk] = make_uint2(pack2(hx,hy), pack2(hz,hw));
                *(uint2*)&Al[row*BKP + lk] = make_uint2(pack2(lx,ly), pack2(lz,lw));
            }
            {
                const int br = b0r + row;
                float4 v = make_float4(0.f, 0.f, 0.f, 0.f);
                if (br < Nlim)
                    v = *(const float4*)(Bm + (size_t)br * ldb + k0 + lk);
                __nv_bfloat16 hx,hy,hz,hw, lx,ly,lz,lw;
                bsplit(v.x,hx,lx); bsplit(v.y,hy,ly);
                bsplit(v.z,hz,lz); bsplit(v.w,hw,lw);
                *(uint2*)&Bh[row*BKP + lk] = make_uint2(pack2(hx,hy), pack2(hz,hw));
                *(uint2*)&Bl[row*BKP + lk] = make_uint2(pack2(lx,ly), pack2(lz,lw));
            }
        }
        __syncthreads();
        #pragma unroll
        for (int kk = 0; kk < 32; kk += 16) {
            uint32_t bh0[4], bh1[4], bl0[4], bl1[4];
            #pragma unroll
            for (int nf = 0; nf < 4; nf++) {
                const int nb = (wn + nf*8 + g)*BKP + kk + 2*tig;
                bh0[nf] = *(const uint32_t*)&Bh[nb];
                bh1[nf] = *(const uint32_t*)&Bh[nb + 8];
                bl0[nf] = *(const uint32_t*)&Bl[nb];
                bl1[nf] = *(const uint32_t*)&Bl[nb + 8];
            }
            #pragma unroll
            for (int mf = 0; mf < 4; mf++) {
                const int rb  = (wm + mf*16 + g)*BKP + kk + 2*tig;
                const int rb8 = rb + 8*BKP;
                const uint32_t ah0 = *(const uint32_t*)&Ah[rb];
                const uint32_t ah1 = *(const uint32_t*)&Ah[rb8];
                const uint32_t ah2 = *(const uint32_t*)&Ah[rb + 8];
                const uint32_t ah3 = *(const uint32_t*)&Ah[rb8 + 8];
                const uint32_t al0 = *(const uint32_t*)&Al[rb];
                const uint32_t al1 = *(const uint32_t*)&Al[rb8];
                const uint32_t al2 = *(const uint32_t*)&Al[rb + 8];
                const uint32_t al3 = *(const uint32_t*)&Al[rb8 + 8];
                #pragma unroll
                for (int nf = 0; nf < 4; nf++) {
                    mma_bf16(acc[mf][nf], ah0,ah1,ah2,ah3, bh0[nf], bh1[nf]);
                    mma_bf16(acc[mf][nf], ah0,ah1,ah2,ah3, bl0[nf], bl1[nf]);
                    mma_bf16(acc[mf][nf], al0,al1,al2,al3, bh0[nf], bh1[nf]);
                }
            }
        }
    }
}

#define GEMM_SMEM \
    __shared__ __nv_bfloat16 Ah[128*BKP], Al[128*BKP], Bh[128*BKP], Bl[128*BKP];

// ---------------------------------------------------------------------------
// K1: fused QKV projection.  out[m][n] = x[m] . W[n] + b[n]
// grid (1536/128=12, 3072/128=24); each N-tile lies inside one of Wq/Wk/Wv.
// ---------------------------------------------------------------------------
__global__ void __launch_bounds__(256, 2)
qkv_kernel(const float* __restrict__ x,
           const float* __restrict__ Wq, const float* __restrict__ bq,
           const float* __restrict__ Wk, const float* __restrict__ bk,
           const float* __restrict__ Wv, const float* __restrict__ bv)
{
    GEMM_SMEM
    const int m0 = blockIdx.y * 128;
    const int n0 = blockIdx.x * 128;
    const int which = n0 >> 9;
    const float* W    = (which == 0) ? Wq : (which == 1) ? Wk : Wv;
    const float* bias = (which == 0) ? bq : (which == 1) ? bk : bv;
    float* dst        = (which == 0) ? g_q : (which == 1) ? g_k : g_v;
    const int e0 = n0 & 511;

    float acc[4][4][4] = {};
    mma128_core(x, KIN, m0, KB*KS, W, KIN, e0, KE, KIN, acc, Ah, Al, Bh, Bl);

    const int lane = threadIdx.x & 31, warp = threadIdx.x >> 5;
    const int wm = (warp >> 2) * 64, wn = (warp & 3) * 32;
    const int g = lane >> 2, tig = lane & 3;
    #pragma unroll
    for (int mf = 0; mf < 4; mf++)
        #pragma unroll
        for (int nf = 0; nf < 4; nf++) {
            const int e = e0 + wn + nf*8 + 2*tig;       // even
            const int h = e >> 6, d0 = e & 63;
            const float2 bv2 = make_float2(bias[e], bias[e+1]);
            #pragma unroll
            for (int half = 0; half < 2; half++) {
                const int m = m0 + wm + mf*16 + g + half*8;
                const int b = m / KS, s = m % KS;
                float2 v;
                v.x = acc[mf][nf][half*2+0] + bv2.x;
                v.y = acc[mf][nf][half*2+1] + bv2.y;
                *(float2*)(dst + ((size_t)(b*KH + h)*KS + s)*KD + d0) = v;
            }
        }
}

// ---------------------------------------------------------------------------
// K2: positional projections PK[t] / PQ[t], t in [0,767).
// grid (1024/128=8, 6).
// ---------------------------------------------------------------------------
__global__ void __launch_bounds__(256, 2)
pos_kernel(const float* __restrict__ rel_table,
           const float* __restrict__ Wpk, const float* __restrict__ bpk,
           const float* __restrict__ Wpq, const float* __restrict__ bpq)
{
    GEMM_SMEM
    const int m0 = blockIdx.y * 128;
    const int n0 = blockIdx.x * 128;
    const bool isq = (n0 >= 512);
    const float* W    = isq ? Wpq : Wpk;
    const float* bias = isq ? bpq : bpk;
    float* dst        = isq ? g_pq : g_pk;
    const int e0 = n0 & 511;

    float acc[4][4][4] = {};
    mma128_core(rel_table + (size_t)KRELOFF*KIN, KIN, m0, KT,
                W, KIN, e0, KE, KIN, acc, Ah, Al, Bh, Bl);

    const int lane = threadIdx.x & 31, warp = threadIdx.x >> 5;
    const int wm = (warp >> 2) * 64, wn = (warp & 3) * 32;
    const int g = lane >> 2, tig = lane & 3;
    #pragma unroll
    for (int mf = 0; mf < 4; mf++)
        #pragma unroll
        for (int nf = 0; nf < 4; nf++) {
            const int e = e0 + wn + nf*8 + 2*tig;
            const int h = e >> 6, d0 = e & 63;
            const float2 bv2 = make_float2(bias[e], bias[e+1]);
            #pragma unroll
            for (int half = 0; half < 2; half++) {
                const int t = m0 + wm + mf*16 + g + half*8;
                if (t >= KT) continue;
                float2 v;
                v.x = acc[mf][nf][half*2+0] + bv2.x;
                v.y = acc[mf][nf][half*2+1] + bv2.y;
                *(float2*)(dst + ((size_t)h*KT + t)*KD + d0) = v;
            }
        }
}

// ---------------------------------------------------------------------------
// K3/K4: disentangled score tables with t-window tile skipping.
//   which==0: C2P[bh][i][t] = q[bh][i] . PK[h][t]   window [383-r_max, 766-i0]
//   which==1: P2C[bh][j][t] = k[bh][j] . PQ[h][t]   window [i0, r_max+383]
// grid (6, 3, 64).
// ---------------------------------------------------------------------------
__global__ void __launch_bounds__(256, 2)
disent_kernel(int which)
{
    const int i0 = blockIdx.y * 128;           // row block base (i or j)
    const int t0 = blockIdx.x * 128;
    const int r_max = (i0 + 127 < KS - 1) ? i0 + 127 : KS - 1;
    int t_lo, t_hi;
    if (which == 0) { t_lo = (KS - 1) - r_max;  t_hi = (2*KS - 2) - i0; }
    else            { t_lo = i0;                t_hi = r_max + (KS - 1); }
    if (t0 > t_hi || t0 + 127 < t_lo) return;  // tile never read

    GEMM_SMEM
    const int bh = blockIdx.z;
    const int h  = bh & 7;
    const float* vecs = which ? g_k  : g_q;
    const float* pos  = which ? g_pq : g_pk;
    float*       out  = which ? g_p2c : g_c2p;

    float acc[4][4][4] = {};
    mma128_core(vecs + (size_t)bh*KS*KD, KD, i0, KS,
                pos  + (size_t)h*KT*KD,  KD, t0, KT, KD, acc, Ah, Al, Bh, Bl);

    const int lane = threadIdx.x & 31, warp = threadIdx.x >> 5;
    const int wm = (warp >> 2) * 64, wn = (warp & 3) * 32;
    const int g = lane >> 2, tig = lane & 3;
    #pragma unroll
    for (int mf = 0; mf < 4; mf++)
        #pragma unroll
        for (int half = 0; half < 2; half++) {
            const int i = i0 + wm + mf*16 + g + half*8;
            float* orow = out + ((size_t)bh*KS + i)*KTP;
            #pragma unroll
            for (int nf = 0; nf < 4; nf++) {
                const int t = t0 + wn + nf*8 + 2*tig;   // even, < KTP
                float2 v;
                v.x = acc[mf][nf][half*2+0];
                v.y = acc[mf][nf][half*2+1];
                *(float2*)(orow + t) = v;
            }
        }
}

// ---------------------------------------------------------------------------
// 64x64 tile scalar core used inside the attention kernel.
// ---------------------------------------------------------------------------
__device__ __forceinline__ void sgemm64_core(
    const float* __restrict__ A, int lda, int a0, int Mlim,
    const float* __restrict__ Bm, int ldb, int b0, int Nlim,
    int K, float acc[4][4], float* As, float* Bs)
{
    const int tid = threadIdx.x;
    const int tx = tid & 15, ty = tid >> 4;
    const int lr = tid >> 2;
    const int lk = (tid & 3) * 4;

    for (int k0 = 0; k0 < K; k0 += 16) {
        __syncthreads();
        {
            int row = a0 + lr;
            float4 v = make_float4(0.f, 0.f, 0.f, 0.f);
            if (row < Mlim)
                v = *(const float4*)(A + (size_t)row * lda + k0 + lk);
            As[(lk+0)*68 + lr] = v.x; As[(lk+1)*68 + lr] = v.y;
            As[(lk+2)*68 + lr] = v.z; As[(lk+3)*68 + lr] = v.w;
        }
        {
            int row = b0 + lr;
            float4 v = make_float4(0.f, 0.f, 0.f, 0.f);
            if (row < Nlim)
                v = *(const float4*)(Bm + (size_t)row * ldb + k0 + lk);
            Bs[(lk+0)*68 + lr] = v.x; Bs[(lk+1)*68 + lr] = v.y;
            Bs[(lk+2)*68 + lr] = v.z; Bs[(lk+3)*68 + lr] = v.w;
        }
        __syncthreads();
        #pragma unroll
        for (int kk = 0; kk < 16; kk++) {
            float4 a4 = *(const float4*)&As[kk*68 + ty*4];
            float4 b4 = *(const float4*)&Bs[kk*68 + tx*4];
            float av[4] = {a4.x, a4.y, a4.z, a4.w};
            float bv[4] = {b4.x, b4.y, b4.z, b4.w};
            #pragma unroll
            for (int r = 0; r < 4; r++)
                #pragma unroll
                for (int c = 0; c < 4; c++)
                    acc[r][c] = fmaf(av[r], bv[c], acc[r][c]);
        }
    }
}

// ---------------------------------------------------------------------------
// K5: flash attention per (i-tile=64, h, b).  Online softmax over 6 j-tiles.
// logits = (qk + c2p_gather + p2c_gather) * SCALE, mask fill -9e15.
// ---------------------------------------------------------------------------
__global__ void attn_kernel(const int* __restrict__ mask)
{
    __shared__ float As[16*68], Bs[16*68];
    __shared__ float Ss[64*65];
    __shared__ float Vs[64*68];          // aliased: p2c band stage, then V tile
    __shared__ float row_m[64], row_l[64], alpha_s[64];
    __shared__ float red[64*4];
    __shared__ int   msks[64];

    const int i0 = blockIdx.x * 64;
    const int h  = blockIdx.y;
    const int b  = blockIdx.z;
    const int bh = b*KH + h;
    const float* qb   = g_q + (size_t)bh*KS*KD;
    const float* kb   = g_k + (size_t)bh*KS*KD;
    const float* vb   = g_v + (size_t)bh*KS*KD;
    const float* c2pb = g_c2p + (size_t)bh*KS*KTP;
    const float* p2cb = g_p2c + (size_t)bh*KS*KTP;

    const int tid = threadIdx.x;
    const int tx = tid & 15, ty = tid >> 4;
    const int rrow = tid >> 2, q4 = tid & 3;   // softmax: 4 threads per row

    float o[4][4] = {};
    if (tid < 64) { row_m[tid] = -1e30f; row_l[tid] = 0.f; }

    for (int j0 = 0; j0 < KS; j0 += 64) {
        // ---- stage p2c diagonal band into Vs (coalesced per j-row) ----
        __syncthreads();
        {
            const int c = rrow;                     // local j
            const int j = j0 + c;
            const float* src = p2cb + (size_t)j*KTP + (j - i0 + 320);
            #pragma unroll
            for (int xx = 0; xx < 16; xx++) {
                const int x = q4 + xx*4;
                Vs[c*68 + x] = src[x];              // t = j-i0+320+x ; x = 63-r
            }
        }
        if (tid < 64) msks[tid] = mask[b*KS + j0 + tid];
        __syncthreads();

        // ---- init acc with c2p (gmem gather) + p2c (staged) ----
        float acc[4][4];
        #pragma unroll
        for (int r = 0; r < 4; r++) {
            const int i = i0 + ty*4 + r;
            const float* crow = c2pb + (size_t)i*KTP + (j0 - i + 383);
            #pragma unroll
            for (int c = 0; c < 4; c++) {
                const int jl = tx*4 + c;
                acc[r][c] = crow[jl] + Vs[jl*68 + 63 - (ty*4 + r)];
            }
        }

        // ---- c2c: q @ k^T ----
        sgemm64_core(qb, KD, i0, KS, kb, KD, j0, KS, KD, acc, As, Bs);

        // ---- scale + mask, write S tile ----
        #pragma unroll
        for (int r = 0; r < 4; r++)
            #pragma unroll
            for (int c = 0; c < 4; c++) {
                float v = acc[r][c] * KSCALE;
                if (msks[tx*4 + c] == 0) v = -9e15f;
                Ss[(ty*4 + r)*65 + tx*4 + c] = v;
            }
        __syncthreads();

        // ---- online softmax (4 threads/row) ----
        {
            float mx = -1e30f;
            #pragma unroll
            for (int jj = q4*16; jj < q4*16 + 16; jj++)
                mx = fmaxf(mx, Ss[rrow*65 + jj]);
            red[rrow*4 + q4] = mx;
        }
        __syncthreads();
        if (q4 == 0) {
            float mn = fmaxf(fmaxf(red[rrow*4+0], red[rrow*4+1]),
                             fmaxf(red[rrow*4+2], red[rrow*4+3]));
            mn = fmaxf(mn, row_m[rrow]);
            alpha_s[rrow] = __expf(row_m[rrow] - mn);
            row_m[rrow] = mn;
        }
        __syncthreads();
        {
            const float mn = row_m[rrow];
            float s = 0.f;
            #pragma unroll
            for (int jj = q4*16; jj < q4*16 + 16; jj++) {
                float p = __expf(Ss[rrow*65 + jj] - mn);
                Ss[rrow*65 + jj] = p;
                s += p;
            }
            red[rrow*4 + q4] = s;
        }
        __syncthreads();
        if (q4 == 0)
            row_l[rrow] = row_l[rrow]*alpha_s[rrow]
                        + red[rrow*4+0] + red[rrow*4+1] + red[rrow*4+2] + red[rrow*4+3];

        // ---- load V tile into Vs (band consumed already) ----
        {
            const int c = rrow, d0 = q4 * 16;
            const float* src = vb + (size_t)(j0 + c)*KD + d0;
            #pragma unroll
            for (int dd = 0; dd < 16; dd += 4)
                *(float4*)&Vs[c*68 + d0 + dd] = *(const float4*)(src + dd);
        }
        __syncthreads();

        // ---- rescale O, accumulate P @ V ----
        float al[4];
        #pragma unroll
        for (int r = 0; r < 4; r++) al[r] = alpha_s[ty*4 + r];
        #pragma unroll
        for (int r = 0; r < 4; r++)
            #pragma unroll
            for (int c = 0; c < 4; c++) o[r][c] *= al[r];

        #pragma unroll
        for (int jj = 0; jj < 64; jj++) {
            float pv[4];
            #pragma unroll
            for (int r = 0; r < 4; r++) pv[r] = Ss[(ty*4 + r)*65 + jj];
            float4 vv = *(const float4*)&Vs[jj*68 + tx*4];
            float vvv[4] = {vv.x, vv.y, vv.z, vv.w};
            #pragma unroll
            for (int r = 0; r < 4; r++)
                #pragma unroll
                for (int c = 0; c < 4; c++)
                    o[r][c] = fmaf(pv[r], vvv[c], o[r][c]);
        }
    }

    // ---- normalize, store ctx [b][s][h*D+d] ----
    float inv[4];
    #pragma unroll
    for (int r = 0; r < 4; r++) inv[r] = 1.f / row_l[ty*4 + r];
    #pragma unroll
    for (int r = 0; r < 4; r++) {
        const int i = i0 + ty*4 + r;
        #pragma unroll
        for (int c = 0; c < 4; c++)
            g_ctx[((size_t)b*KS + i)*KE + h*KD + tx*4 + c] = o[r][c] * inv[r];
    }
}

// ---------------------------------------------------------------------------
// K6: output projection: out = ctx @ Wo^T + bo
// grid (512/128=4, 3072/128=24).
// ---------------------------------------------------------------------------
__global__ void __launch_bounds__(256, 2)
out_kernel(const float* __restrict__ Wo, const float* __restrict__ bo,
           float* __restrict__ out)
{
    GEMM_SMEM
    const int m0 = blockIdx.y * 128;
    const int n0 = blockIdx.x * 128;

    float acc[4][4][4] = {};
    mma128_core(g_ctx, KE, m0, KB*KS, Wo, KE, n0, KIN, KE, acc, Ah, Al, Bh, Bl);

    const int lane = threadIdx.x & 31, warp = threadIdx.x >> 5;
    const int wm = (warp >> 2) * 64, wn = (warp & 3) * 32;
    const int g = lane >> 2, tig = lane & 3;
    #pragma unroll
    for (int mf = 0; mf < 4; mf++)
        #pragma unroll
        for (int nf = 0; nf < 4; nf++) {
            const int n = n0 + wn + nf*8 + 2*tig;
            const float2 bv2 = make_float2(bo[n], bo[n+1]);
            #pragma unroll
            for (int half = 0; half < 2; half++) {
                const int m = m0 + wm + mf*16 + g + half*8;
                float2 v;
                v.x = acc[mf][nf][half*2+0] + bv2.x;
                v.y = acc[mf][nf][half*2+1] + bv2.y;
                *(float2*)(out + (size_t)m*KIN + n) = v;
            }
        }
}

// ---------------------------------------------------------------------------
extern "C" void kernel_launch(void* const* d_in, const int* in_sizes, int n_in,
                              void* d_out, int out_size)
{
    const float* x    = (const float*)d_in[0];
    const int*   mask = (const int*)  d_in[1];
    const float* Wq   = (const float*)d_in[2];
    const float* bq   = (const float*)d_in[3];
    const float* Wk   = (const float*)d_in[4];
    const float* bk   = (const float*)d_in[5];
    const float* Wv   = (const float*)d_in[6];
    const float* bv   = (const float*)d_in[7];
    const float* rel  = (const float*)d_in[8];
    const float* Wpk  = (const float*)d_in[9];
    const float* bpk  = (const float*)d_in[10];
    const float* Wpq  = (const float*)d_in[11];
    const float* bpq  = (const float*)d_in[12];
    const float* Wo   = (const float*)d_in[13];
    const float* bo   = (const float*)d_in[14];

    dim3 thr(256);
    qkv_kernel   <<<dim3(1536/128, (KB*KS)/128), thr>>>(x, Wq, bq, Wk, bk, Wv, bv);
    pos_kernel   <<<dim3(1024/128, (KT + 127)/128), thr>>>(rel, Wpk, bpk, Wpq, bpq);
    disent_kernel<<<dim3((KT + 127)/128, KS/128, KB*KH), thr>>>(0);
    disent_kernel<<<dim3((KT + 127)/128, KS/128, KB*KH), thr>>>(1);
    attn_kernel  <<<dim3(KS/64, KH, KB), thr>>>(mask);
    out_kernel   <<<dim3(KIN/128, (KB*KS)/128), thr>>>(Wo, bo, (float*)d_out);
}